// round 13
// baseline (speedup 1.0000x reference)
#include <cuda_runtime.h>
#include <cuda_bf16.h>
#include <cuda_fp16.h>
#include <math.h>
#include <stdint.h>

#define BB 4
#define NN 1024
#define DIMD 512
#define HH 8
#define DHD 64
#define INNERD 512
#define BH (BB*HH)            // 32
#define NROWS (BH*NN)         // 32768
#define SCALE 0.125f

// ---------------- scratch (device globals; no runtime allocation) ----------
__device__ float g_qni[NROWS];              // reciprocal q norms
__device__ float g_kni[NROWS];              // reciprocal k norms
__device__ float g_clus[NROWS];
__device__ int   g_msum;                    // 8 * sum(mask)
__device__ float g_attn_fb[(size_t)BH*NN*NN];
// bf16 split operands
__device__ __nv_bfloat16 g_x_hi[(size_t)BB*NN*DIMD];
__device__ __nv_bfloat16 g_x_lo[(size_t)BB*NN*DIMD];
__device__ __nv_bfloat16 g_wt_hi[4*512*512];   // W^T [n][k], slots q,k,v,o
__device__ __nv_bfloat16 g_wt_lo[4*512*512];
__device__ __nv_bfloat16 g_ctx_hi[(size_t)BB*NN*INNERD];
__device__ __nv_bfloat16 g_ctx_lo[(size_t)BB*NN*INNERD];
__device__ __nv_bfloat16 g_q_hi[NROWS*DHD];    // [bh][n][d]
__device__ __nv_bfloat16 g_q_lo[NROWS*DHD];
__device__ __nv_bfloat16 g_k_hi[NROWS*DHD];    // [bh][n][d]
__device__ __nv_bfloat16 g_k_lo[NROWS*DHD];
__device__ __half        g_vt_h[NROWS*DHD];    // fp16 TRANSPOSED [bh][d][n]

// ---------------- helpers ----------------
__device__ __forceinline__ uint32_t smem_to_u32(const void* p) {
    uint32_t a;
    asm("{ .reg .u64 t; cvta.to.shared.u64 t, %1; cvt.u32.u64 %0, t; }"
        : "=r"(a) : "l"(p));
    return a;
}
#define SMEM_SWZ(off) ((off) ^ (((off) >> 3) & 0x70))

#define LDSM4(R0, R1, R2, R3, ADDR) \
    asm volatile("ldmatrix.sync.aligned.m8n8.x4.shared.b16 {%0,%1,%2,%3}, [%4];" \
        : "=r"(R0), "=r"(R1), "=r"(R2), "=r"(R3) : "r"(ADDR))

#define MMA16816(C, A, B0, B1) \
    asm volatile("mma.sync.aligned.m16n8k16.row.col.f32.bf16.bf16.f32 " \
        "{%0,%1,%2,%3}, {%4,%5,%6,%7}, {%8,%9}, {%0,%1,%2,%3};" \
        : "+f"((C)[0]), "+f"((C)[1]), "+f"((C)[2]), "+f"((C)[3]) \
        : "r"((A)[0]), "r"((A)[1]), "r"((A)[2]), "r"((A)[3]), "r"(B0), "r"(B1))

#define MMA16816H(C, A, B0, B1) \
    asm volatile("mma.sync.aligned.m16n8k16.row.col.f32.f16.f16.f32 " \
        "{%0,%1,%2,%3}, {%4,%5,%6,%7}, {%8,%9}, {%0,%1,%2,%3};" \
        : "+f"((C)[0]), "+f"((C)[1]), "+f"((C)[2]), "+f"((C)[3]) \
        : "r"((A)[0]), "r"((A)[1]), "r"((A)[2]), "r"((A)[3]), "r"(B0), "r"(B1))

#define CP_ASYNC16(smaddr, gptr) \
    asm volatile("cp.async.cg.shared.global [%0], [%1], 16;" \
        :: "r"(smaddr), "l"(gptr) : "memory")
#define CP_COMMIT() asm volatile("cp.async.commit_group;" ::: "memory")
#define CP_WAIT1() asm volatile("cp.async.wait_group 1;" ::: "memory")
#define CP_WAIT0() asm volatile("cp.async.wait_group 0;" ::: "memory")

// FMA-pipe exp (no MUFU)
__device__ __forceinline__ float fexp(float x) {
    float t = x * 1.4426950408889634f;
    float z = t + 12582912.0f;
    int ni = __float_as_int(z) << 23;
    float f = t - (z - 12582912.0f);
    float p =            1.3333558e-3f;
    p = fmaf(p, f, 9.6181291e-3f);
    p = fmaf(p, f, 5.5504110e-2f);
    p = fmaf(p, f, 2.4022651e-1f);
    p = fmaf(p, f, 6.9314718e-1f);
    p = fmaf(p, f, 1.0f);
    return __int_as_float(__float_as_int(p) + ni);
}

__device__ __forceinline__ void split_store4(__nv_bfloat16* hp, __nv_bfloat16* lp,
                                             float v0, float v1, float v2, float v3)
{
    __nv_bfloat16 h0 = __float2bfloat16(v0), h1 = __float2bfloat16(v1);
    __nv_bfloat16 h2 = __float2bfloat16(v2), h3 = __float2bfloat16(v3);
    *(__nv_bfloat162*)(hp)     = __halves2bfloat162(h0, h1);
    *(__nv_bfloat162*)(hp + 2) = __halves2bfloat162(h2, h3);
    *(__nv_bfloat162*)(lp)     = __halves2bfloat162(
        __float2bfloat16(v0 - __bfloat162float(h0)),
        __float2bfloat16(v1 - __bfloat162float(h1)));
    *(__nv_bfloat162*)(lp + 2) = __halves2bfloat162(
        __float2bfloat16(v2 - __bfloat162float(h2)),
        __float2bfloat16(v3 - __bfloat162float(h3)));
}

// ---------------- init ----------------
__global__ void init_kernel() {
    if (threadIdx.x == 0 && blockIdx.x == 0) g_msum = 0;
}

// ---------------- convert x -> hi/lo bf16 ----------------
__global__ void convx_kernel(const float* __restrict__ x) {
    int i = blockIdx.x * blockDim.x + threadIdx.x;
    float4 v = ((const float4*)x)[i];
    split_store4(g_x_hi + (size_t)i * 4, g_x_lo + (size_t)i * 4,
                 v.x, v.y, v.z, v.w);
}

// ---------------- transpose+convert W -> W^T hi/lo bf16 ----------------
__global__ void convw_kernel(const float* __restrict__ Wq,
                             const float* __restrict__ Wk,
                             const float* __restrict__ Wv,
                             const float* __restrict__ Wo)
{
    __shared__ float tile[32][33];
    const int z = blockIdx.z;
    const float* W = (z == 0) ? Wq : (z == 1) ? Wk : (z == 2) ? Wv : Wo;
    const int tx = threadIdx.x, ty = threadIdx.y;
    const int bk = blockIdx.y * 32, bn = blockIdx.x * 32;
    #pragma unroll
    for (int r = 0; r < 4; r++)
        tile[ty + 8*r][tx] = W[(size_t)(bk + ty + 8*r) * 512 + bn + tx];
    __syncthreads();
    #pragma unroll
    for (int r = 0; r < 4; r++) {
        int n = bn + ty + 8*r, k = bk + tx;
        float v = tile[tx][ty + 8*r];
        __nv_bfloat16 h = __float2bfloat16(v);
        size_t o = (size_t)z * 262144 + (size_t)n * 512 + k;
        g_wt_hi[o] = h;
        g_wt_lo[o] = __float2bfloat16(v - __bfloat162float(h));
    }
}

// ================= HMMA projection GEMM, 128x64 tile, occ 2 =================
#define SA_HI 0
#define SA_LO 16384
#define SB_HI 32768
#define SB_LO 40960
#define STAGE_B 49152
#define BMMA_SMEM (2*STAGE_B)

__global__ __launch_bounds__(256, 2)
void bmma_kernel(const float* __restrict__ b0, const float* __restrict__ b1,
                 const float* __restrict__ b2, float* __restrict__ out, int mode)
{
    extern __shared__ char smc[];
    const uint32_t smb = smem_to_u32(smc);
    const int tid = threadIdx.x;
    const int wid = tid >> 5, lane = tid & 31;
    const int z = (mode < 0) ? (int)blockIdx.z : mode;
    const int bm = blockIdx.y * 128, bn = blockIdx.x * 64;

    const __nv_bfloat16* Ah = (z == 3) ? g_ctx_hi : g_x_hi;
    const __nv_bfloat16* Al = (z == 3) ? g_ctx_lo : g_x_lo;
    const __nv_bfloat16* Bh = g_wt_hi + (size_t)z * 262144;
    const __nv_bfloat16* Bl = g_wt_lo + (size_t)z * 262144;
    const float* bias = (z == 0) ? b0 : (z == 1) ? b1 : (z == 2) ? b2 : b0;

    float acc[8][4] = {};
    const int ldr = tid >> 3, ldu = tid & 7;

    auto issue = [&](int kc, int st) {
        const uint32_t sb = smb + st * STAGE_B;
        #pragma unroll
        for (int it = 0; it < 4; it++) {
            int r = ldr + it * 32;
            size_t ga = (size_t)(bm + r) * 512 + kc * 64 + ldu * 8;
            uint32_t so = SMEM_SWZ((uint32_t)(r * 128 + ldu * 16));
            CP_ASYNC16(sb + SA_HI + so, Ah + ga);
            CP_ASYNC16(sb + SA_LO + so, Al + ga);
        }
        #pragma unroll
        for (int it = 0; it < 2; it++) {
            int r = ldr + it * 32;
            size_t gb = (size_t)(bn + r) * 512 + kc * 64 + ldu * 8;
            uint32_t so = SMEM_SWZ((uint32_t)(r * 128 + ldu * 16));
            CP_ASYNC16(sb + SB_HI + so, Bh + gb);
            CP_ASYNC16(sb + SB_LO + so, Bl + gb);
        }
        CP_COMMIT();
    };

    issue(0, 0);
    for (int kc = 0; kc < 8; kc++) {
        const int st = kc & 1;
        const uint32_t sb = smb + st * STAGE_B;
        if (kc < 7) { issue(kc + 1, st ^ 1); CP_WAIT1(); }
        else        { CP_WAIT0(); }
        __syncthreads();

        #pragma unroll
        for (int ks = 0; ks < 4; ks++) {
            uint32_t ah[4], al[4], bhf[8][2], blf[8][2];
            const int arow = wid * 16 + (lane & 15);
            const int akb  = ks * 32 + (lane >> 4) * 16;
            {
                uint32_t off = SMEM_SWZ((uint32_t)(arow * 128 + akb));
                LDSM4(ah[0], ah[1], ah[2], ah[3], sb + SA_HI + off);
                LDSM4(al[0], al[1], al[2], al[3], sb + SA_LO + off);
            }
            const int lr = lane & 7, sel = lane >> 3;
            const int nrow = ((sel >> 1) & 1) * 8 + lr;
            const int bkb  = ks * 32 + (sel & 1) * 16;
            #pragma unroll
            for (int p = 0; p < 4; p++) {
                uint32_t off = SMEM_SWZ((uint32_t)((nrow + p * 16) * 128 + bkb));
                LDSM4(bhf[2*p][0], bhf[2*p][1], bhf[2*p+1][0], bhf[2*p+1][1],
                      sb + SB_HI + off);
                LDSM4(blf[2*p][0], blf[2*p][1], blf[2*p+1][0], blf[2*p+1][1],
                      sb + SB_LO + off);
            }
            #pragma unroll
            for (int nb = 0; nb < 8; nb++) {
                MMA16816(acc[nb], ah, bhf[nb][0], bhf[nb][1]);
                MMA16816(acc[nb], ah, blf[nb][0], blf[nb][1]);
                MMA16816(acc[nb], al, bhf[nb][0], bhf[nb][1]);
            }
        }
        __syncthreads();
    }

    // ---------------- epilogue ----------------
    const int g = lane >> 2, t = lane & 3;
    const int h = bn >> 6;
    float2 bv[8];
    #pragma unroll
    for (int nb = 0; nb < 8; nb++)
        bv[nb] = *(const float2*)&bias[bn + nb * 8 + 2 * t];

    #pragma unroll
    for (int half = 0; half < 2; half++) {
        const int rglob = bm + wid * 16 + g + half * 8;
        const int bi = rglob >> 10, n = rglob & 1023;
        float ss = 0.f;
        #pragma unroll
        for (int nb = 0; nb < 8; nb++) {
            float v0 = acc[nb][half * 2 + 0] + bv[nb].x;
            float v1 = acc[nb][half * 2 + 1] + bv[nb].y;
            ss += v0 * v0 + v1 * v1;
            const int d = nb * 8 + 2 * t;
            if (z == 3) {
                *(float2*)(out + (size_t)rglob * 512 + bn + d) =
                    make_float2(v0, v1);
            } else if (z == 2) {
                size_t vb = ((size_t)(bi*HH + h)*DHD + d)*NN + n;
                g_vt_h[vb]      = __float2half_rn(v0);
                g_vt_h[vb + NN] = __float2half_rn(v1);
            } else {
                __nv_bfloat16 h0 = __float2bfloat16(v0);
                __nv_bfloat16 h1 = __float2bfloat16(v1);
                __nv_bfloat16 l0 = __float2bfloat16(v0 - __bfloat162float(h0));
                __nv_bfloat16 l1 = __float2bfloat16(v1 - __bfloat162float(h1));
                __nv_bfloat16* dh = (z == 0) ? g_q_hi : g_k_hi;
                __nv_bfloat16* dl = (z == 0) ? g_q_lo : g_k_lo;
                size_t qb = ((size_t)(bi*HH + h)*NN + n)*DHD + d;
                *(__nv_bfloat162*)(dh + qb) = __halves2bfloat162(h0, h1);
                *(__nv_bfloat162*)(dl + qb) = __halves2bfloat162(l0, l1);
            }
        }
        if (z < 2) {
            ss += __shfl_xor_sync(0xffffffffu, ss, 1);
            ss += __shfl_xor_sync(0xffffffffu, ss, 2);
            if (t == 0) {
                float* dst = (z == 0) ? g_qni : g_kni;
                dst[(bi * HH + h) * NN + n] = rsqrtf(ss);
            }
        }
    }
}

// ============ fused attention, occ=2: fp16 es, overlapped stores ============
#define ES_B 2064
#define KT_B 144
#define VT_B 272
#define STG_LO2 9216
#define OFF_ES  0
#define OFF_ST0 66048
#define OFF_ST1 84480
#define OFF_RED 102912
#define OFF_INVS 105984
#define OFF_WCNT 106112
#define ATTN_SMEM 106496

__global__ __launch_bounds__(256, 2)
void attn4_kernel(const int* __restrict__ mask, float* __restrict__ attn_out)
{
    extern __shared__ char smc[];
    const uint32_t smb = smem_to_u32(smc);
    float* invs = (float*)(smc + OFF_INVS);
    float* red  = (float*)(smc + OFF_RED);
    int*   wcnt = (int*)(smc + OFF_WCNT);

    const int tid  = threadIdx.x;
    const int warp = tid >> 5, lane = tid & 31;
    const int g = lane >> 2, t = lane & 3;
    const int lr = lane & 7, sel = lane >> 3;
    const int blk = blockIdx.x;             // 1024
    const int bh  = blk >> 5;
    const int i0  = (blk & 31) * 32;
    const int b   = bh >> 3;

    const uint32_t stg[2] = {smb + OFF_ST0, smb + OFF_ST1};

    auto issueK = [&](int jt, uint32_t sb) {
        #pragma unroll
        for (int it = 0; it < 2; it++) {
            int idx = tid + it * 256;
            int r = idx >> 3, u = idx & 7;
            size_t gk = ((size_t)(bh * NN + jt * 64 + r)) * DHD + u * 8;
            CP_ASYNC16(sb + r * KT_B + u * 16, g_k_hi + gk);
            CP_ASYNC16(sb + STG_LO2 + r * KT_B + u * 16, g_k_lo + gk);
        }
        CP_COMMIT();
    };
    auto issueV = [&](int jt, uint32_t sb) {
        #pragma unroll
        for (int it = 0; it < 4; it++) {
            int idx = tid + it * 256;
            int d = idx >> 4, u = idx & 15;
            size_t gv = ((size_t)bh * DHD + d) * NN + jt * 128 + u * 8;
            CP_ASYNC16(sb + d * VT_B + u * 16, g_vt_h + gv);
        }
        CP_COMMIT();
    };

    issueK(0, stg[0]);
    {
        int r = tid >> 3, u = tid & 7;
        size_t gq = ((size_t)(bh * NN + i0 + r)) * DHD + u * 8;
        *(uint4*)(smc + OFF_ST1 + r * KT_B + u * 16) = *(const uint4*)(g_q_hi + gq);
        *(uint4*)(smc + OFF_ST1 + 4608 + r * KT_B + u * 16) = *(const uint4*)(g_q_lo + gq);
    }
    __syncthreads();
    uint32_t qh[2][4][4], ql[2][4][4];
    #pragma unroll
    for (int m = 0; m < 2; m++)
        #pragma unroll
        for (int ks = 0; ks < 4; ks++) {
            uint32_t a = smb + OFF_ST1 + (m * 16 + (lane & 15)) * KT_B
                       + ks * 32 + (lane >> 4) * 16;
            LDSM4(qh[m][ks][0], qh[m][ks][1], qh[m][ks][2], qh[m][ks][3], a);
            LDSM4(ql[m][ks][0], ql[m][ks][1], ql[m][ks][2], ql[m][ks][3], a + 4608);
        }
    __syncthreads();
    issueK(1, stg[1]);

    float qn10[2][2];
    #pragma unroll
    for (int m = 0; m < 2; m++)
        #pragma unroll
        for (int hf = 0; hf < 2; hf++)
            qn10[m][hf] = g_qni[bh * NN + i0 + m * 16 + g + hf * 8] * 10.0f;

    float rall[2][2] = {}, rpos[2][2] = {}, rsum[2][2] = {};
    int cnt = 0;

    // ---- Phase A: copies overlap exp epilogue ----
    for (int jt = 0; jt < 16; jt++) {
        if (jt < 15) CP_WAIT1(); else CP_WAIT0();
        __syncthreads();
        const uint32_t sb = stg[jt & 1];

        float acc[2][4] = {};
        #pragma unroll
        for (int kp = 0; kp < 2; kp++) {
            uint32_t kh4[4], kl4[4];
            uint32_t ka = sb + (warp * 8 + lr) * KT_B + kp * 64 + sel * 16;
            LDSM4(kh4[0], kh4[1], kh4[2], kh4[3], ka);
            LDSM4(kl4[0], kl4[1], kl4[2], kl4[3], ka + STG_LO2);
            #pragma unroll
            for (int h2 = 0; h2 < 2; h2++) {
                const int ks = kp * 2 + h2;
                #pragma unroll
                for (int m = 0; m < 2; m++) {
                    MMA16816(acc[m], qh[m][ks], kh4[h2*2], kh4[h2*2+1]);
                    MMA16816(acc[m], qh[m][ks], kl4[h2*2], kl4[h2*2+1]);
                    MMA16816(acc[m], ql[m][ks], kh4[h2*2], kh4[h2*2+1]);
                }
            }
        }
        __syncthreads();                       // stage consumed
        if (jt + 2 <= 15) issueK(jt + 2, stg[jt & 1]);  // fill under epilogue

        const int j0 = jt * 64 + warp * 8 + t * 2;
        float2 kn = *(const float2*)&g_kni[bh * NN + j0];
        #pragma unroll
        for (int m = 0; m < 2; m++)
            #pragma unroll
            for (int hf = 0; hf < 2; hf++) {
                const int il = m * 16 + g + hf * 8;
                int2 mm = *(const int2*)(mask +
                          ((size_t)(b * NN + i0 + il)) * NN + j0);
                float d0 = acc[m][hf * 2 + 0];
                float d1 = acc[m][hf * 2 + 1];
                float qn = qn10[m][hf];
                float ec0 = fexp(d0 * qn * kn.x);
                float ec1 = fexp(d1 * qn * kn.y);
                rall[m][hf] += ec0 + ec1;
                rpos[m][hf] += (mm.x ? ec0 : 0.f) + (mm.y ? ec1 : 0.f);
                cnt += (mm.x != 0) + (mm.y != 0);
                float es0 = mm.x ? fexp(d0 * SCALE) : 0.f;
                float es1 = mm.y ? fexp(d1 * SCALE) : 0.f;
                rsum[m][hf] += es0 + es1;
                *(__half2*)(smc + OFF_ES + il * ES_B + j0 * 2) =
                    __floats2half2_rn(es0, es1);
            }
    }

    #pragma unroll
    for (int m = 0; m < 2; m++)
        #pragma unroll
        for (int hf = 0; hf < 2; hf++) {
            #pragma unroll
            for (int o = 1; o <= 2; o <<= 1) {
                rall[m][hf] += __shfl_xor_sync(0xffffffffu, rall[m][hf], o);
                rpos[m][hf] += __shfl_xor_sync(0xffffffffu, rpos[m][hf], o);
                rsum[m][hf] += __shfl_xor_sync(0xffffffffu, rsum[m][hf], o);
            }
        }
    #pragma unroll
    for (int o = 16; o > 0; o >>= 1)
        cnt += __shfl_xor_sync(0xffffffffu, cnt, o);
    if (t == 0) {
        #pragma unroll
        for (int m = 0; m < 2; m++)
            #pragma unroll
            for (int hf = 0; hf < 2; hf++) {
                int il = m * 16 + g + hf * 8;
                red[(warp * 32 + il) * 3 + 0] = rall[m][hf];
                red[(warp * 32 + il) * 3 + 1] = rpos[m][hf];
                red[(warp * 32 + il) * 3 + 2] = rsum[m][hf];
            }
    }
    if (lane == 0) wcnt[warp] = cnt;
    __syncthreads();
    if (tid < 32) {
        float a = 0.f, p = 0.f, s = 0.f;
        #pragma unroll
        for (int w = 0; w < 8; w++) {
            a += red[(w * 32 + tid) * 3 + 0];
            p += red[(w * 32 + tid) * 3 + 1];
            s += red[(w * 32 + tid) * 3 + 2];
        }
        invs[tid] = __frcp_rn(s);
        g_clus[bh * NN + i0 + tid] = -__logf(__fdividef(p, a));
    }
    if (tid == 32) {
        int s = 0;
        #pragma unroll
        for (int w = 0; w < 8; w++) s += wcnt[w];
        atomicAdd(&g_msum, s);
    }
    __syncthreads();

    // ---- Phase B: ctx = es @ V; attn gmem write interleaved under MMAs ----
    issueV(0, stg[0]);
    issueV(1, stg[1]);
    const int wm = warp >> 2, wd = warp & 3;
    float acc2[2][4] = {};

    for (int jt = 0; jt < 8; jt++) {
        if (jt < 7) CP_WAIT1(); else CP_WAIT0();
        __syncthreads();
        const uint32_t sb = stg[jt & 1];

        #pragma unroll
        for (int ks2 = 0; ks2 < 8; ks2++) {
            uint32_t ah[4], vh4[4];
            uint32_t aa = smb + OFF_ES + (wm * 16 + (lane & 15)) * ES_B
                        + jt * 256 + ks2 * 32 + (lane >> 4) * 16;
            LDSM4(ah[0], ah[1], ah[2], ah[3], aa);
            uint32_t va = sb + (wd * 16 + ((sel >> 1) & 1) * 8 + lr) * VT_B
                        + ks2 * 32 + (sel & 1) * 16;
            LDSM4(vh4[0], vh4[1], vh4[2], vh4[3], va);
            #pragma unroll
            for (int nb = 0; nb < 2; nb++)
                MMA16816H(acc2[nb], ah, vh4[nb*2], vh4[nb*2+1]);
        }
        __syncthreads();
        if (jt + 2 <= 7) issueV(jt + 2, stg[jt & 1]);

        // attn write chunk jt (fire-and-forget STG drains under next MMAs)
        #pragma unroll
        for (int it = 0; it < 2; it++) {
            int idx = tid + (jt * 2 + it) * 256;   // 4096 units over 8 jt
            int row = idx >> 7, u = idx & 127;
            uint4 vh = *(const uint4*)(smc + OFF_ES + row * ES_B + u * 16);
            float s = invs[row];
            const __half2* ph = (const __half2*)&vh;
            float ov[8];
            #pragma unroll
            for (int p2 = 0; p2 < 4; p2++) {
                float2 f = __half22float2(ph[p2]);
                ov[2*p2+0] = f.x * s;
                ov[2*p2+1] = f.y * s;
            }
            float* dst = attn_out + ((size_t)bh * NN + i0 + row) * NN + u * 8;
            *(float4*)dst       = make_float4(ov[0], ov[1], ov[2], ov[3]);
            *(float4*)(dst + 4) = make_float4(ov[4], ov[5], ov[6], ov[7]);
        }
    }

    const int h = bh & 7;
    #pragma unroll
    for (int nb = 0; nb < 2; nb++)
        #pragma unroll
        for (int hf = 0; hf < 2; hf++) {
            int i = wm * 16 + g + hf * 8;
            int d = wd * 16 + nb * 8 + t * 2;
            float s = invs[i];
            float v0 = acc2[nb][hf * 2 + 0] * s;
            float v1 = acc2[nb][hf * 2 + 1] * s;
            size_t base = ((size_t)(b * NN + i0 + i)) * INNERD + h * DHD + d;
            __nv_bfloat16 h0 = __float2bfloat16(v0);
            __nv_bfloat16 h1 = __float2bfloat16(v1);
            *(__nv_bfloat162*)(g_ctx_hi + base) = __halves2bfloat162(h0, h1);
            *(__nv_bfloat162*)(g_ctx_lo + base) = __halves2bfloat162(
                __float2bfloat16(v0 - __bfloat162float(h0)),
                __float2bfloat16(v1 - __bfloat162float(h1)));
        }
}

// ---------------- final dcl scalar ----------------
__global__ void dcl_kernel(float* out_dcl) {
    __shared__ float red[1024];
    const int tid = threadIdx.x;
    float s = 0.f;
    const int base = tid * 32;
    #pragma unroll 8
    for (int i = 0; i < 32; i++) s += g_clus[base + i];
    red[tid] = s;
    __syncthreads();
    for (int o = 512; o > 0; o >>= 1) {
        if (tid < o) red[tid] += red[tid + o];
        __syncthreads();
    }
    if (tid == 0 && out_dcl) {
        float clus_mean = red[0] / (float)NROWS;
        float regular = ((float)(g_msum >> 3) - (float)(BB * NN)) /
                        ((float)BB * (float)NN * (float)(NN - 1));
        out_dcl[0] = clus_mean + 0.3f * regular;
    }
}

// ---------------- launcher ----------------
extern "C" void kernel_launch(void* const* d_in, const int* in_sizes, int n_in,
                              void* d_out, int out_size) {
    const float* x   = (const float*)d_in[0];
    const int*   msk = (const int*)  d_in[1];
    const float* Wq  = (const float*)d_in[2];
    const float* bq  = (const float*)d_in[3];
    const float* Wk  = (const float*)d_in[4];
    const float* bk  = (const float*)d_in[5];
    const float* Wv  = (const float*)d_in[6];
    const float* bv  = (const float*)d_in[7];
    const float* Wo  = (const float*)d_in[8];
    const float* bo  = (const float*)d_in[9];
    float* out = (float*)d_out;

    const size_t OUTE  = (size_t)BB * NN * DIMD;
    const size_t ATTNE = (size_t)BH * NN * NN;

    float* attn_ptr;
    if ((size_t)out_size >= OUTE + ATTNE) {
        attn_ptr = out + OUTE;
    } else {
        void* p = nullptr;
        cudaGetSymbolAddress(&p, g_attn_fb);
        attn_ptr = (float*)p;
    }
    float* dcl_ptr = ((size_t)out_size >= OUTE + ATTNE + 1) ? (out + OUTE + ATTNE)
                                                            : nullptr;

    cudaFuncSetAttribute(attn4_kernel,
                         cudaFuncAttributeMaxDynamicSharedMemorySize, ATTN_SMEM);
    cudaFuncSetAttribute(bmma_kernel,
                         cudaFuncAttributeMaxDynamicSharedMemorySize, BMMA_SMEM);

    init_kernel<<<1, 32>>>();
    convx_kernel<<<2048, 256>>>(x);
    convw_kernel<<<dim3(16, 16, 4), dim3(32, 8)>>>(Wq, Wk, Wv, Wo);

    dim3 qkvgrid(DIMD / 64, (BB * NN) / 128, 3);   // (8, 32, 3)
    bmma_kernel<<<qkvgrid, 256, BMMA_SMEM>>>(bq, bk, bv, nullptr, -1);

    attn4_kernel<<<BH * (NN / 32), 256, ATTN_SMEM>>>(msk, attn_ptr);

    dim3 ogrid(DIMD / 64, (BB * NN) / 128, 1);     // (8, 32)
    bmma_kernel<<<ogrid, 256, BMMA_SMEM>>>(bo, bo, bo, out, 3);

    dcl_kernel<<<1, 1024>>>(dcl_ptr);
}

// round 14
// speedup vs baseline: 1.0632x; 1.0632x over previous
#include <cuda_runtime.h>
#include <cuda_bf16.h>
#include <cuda_fp16.h>
#include <math.h>
#include <stdint.h>

#define BB 4
#define NN 1024
#define DIMD 512
#define HH 8
#define DHD 64
#define INNERD 512
#define BH (BB*HH)            // 32
#define NROWS (BH*NN)         // 32768
#define SCALE 0.125f

// ---------------- scratch (device globals; no runtime allocation) ----------
__device__ float g_qni[NROWS];              // reciprocal q norms
__device__ float g_kni[NROWS];              // reciprocal k norms
__device__ float g_clus[NROWS];
__device__ int   g_msum;                    // 8 * sum(mask)
__device__ float g_attn_fb[(size_t)BH*NN*NN];
// bf16 split operands
__device__ __nv_bfloat16 g_x_hi[(size_t)BB*NN*DIMD];
__device__ __nv_bfloat16 g_x_lo[(size_t)BB*NN*DIMD];
__device__ __nv_bfloat16 g_wt_hi[3*512*512];   // W^T [n][k], slots q,k,v
__device__ __nv_bfloat16 g_wt_lo[3*512*512];
__device__ __half        g_wo_hi[512*512];     // Wo^T fp16 hi
__device__ __half        g_wo_lo[512*512];     // Wo^T fp16 lo
__device__ __half        g_ctx_h[(size_t)BB*NN*INNERD];   // fp16 ctx
__device__ __nv_bfloat16 g_q_hi[NROWS*DHD];    // [bh][n][d]
__device__ __nv_bfloat16 g_q_lo[NROWS*DHD];
__device__ __nv_bfloat16 g_k_hi[NROWS*DHD];    // [bh][n][d]
__device__ __nv_bfloat16 g_k_lo[NROWS*DHD];
__device__ __half        g_vt_h[NROWS*DHD];    // fp16 TRANSPOSED [bh][d][n]

// ---------------- helpers ----------------
__device__ __forceinline__ uint32_t smem_to_u32(const void* p) {
    uint32_t a;
    asm("{ .reg .u64 t; cvta.to.shared.u64 t, %1; cvt.u32.u64 %0, t; }"
        : "=r"(a) : "l"(p));
    return a;
}
#define SMEM_SWZ(off) ((off) ^ (((off) >> 3) & 0x70))

#define LDSM4(R0, R1, R2, R3, ADDR) \
    asm volatile("ldmatrix.sync.aligned.m8n8.x4.shared.b16 {%0,%1,%2,%3}, [%4];" \
        : "=r"(R0), "=r"(R1), "=r"(R2), "=r"(R3) : "r"(ADDR))

#define MMA16816(C, A, B0, B1) \
    asm volatile("mma.sync.aligned.m16n8k16.row.col.f32.bf16.bf16.f32 " \
        "{%0,%1,%2,%3}, {%4,%5,%6,%7}, {%8,%9}, {%0,%1,%2,%3};" \
        : "+f"((C)[0]), "+f"((C)[1]), "+f"((C)[2]), "+f"((C)[3]) \
        : "r"((A)[0]), "r"((A)[1]), "r"((A)[2]), "r"((A)[3]), "r"(B0), "r"(B1))

#define MMA16816H(C, A, B0, B1) \
    asm volatile("mma.sync.aligned.m16n8k16.row.col.f32.f16.f16.f32 " \
        "{%0,%1,%2,%3}, {%4,%5,%6,%7}, {%8,%9}, {%0,%1,%2,%3};" \
        : "+f"((C)[0]), "+f"((C)[1]), "+f"((C)[2]), "+f"((C)[3]) \
        : "r"((A)[0]), "r"((A)[1]), "r"((A)[2]), "r"((A)[3]), "r"(B0), "r"(B1))

#define CP_ASYNC16(smaddr, gptr) \
    asm volatile("cp.async.cg.shared.global [%0], [%1], 16;" \
        :: "r"(smaddr), "l"(gptr) : "memory")
#define CP_COMMIT() asm volatile("cp.async.commit_group;" ::: "memory")
#define CP_WAIT1() asm volatile("cp.async.wait_group 1;" ::: "memory")
#define CP_WAIT0() asm volatile("cp.async.wait_group 0;" ::: "memory")

// FMA-pipe exp (no MUFU)
__device__ __forceinline__ float fexp(float x) {
    float t = x * 1.4426950408889634f;
    float z = t + 12582912.0f;
    int ni = __float_as_int(z) << 23;
    float f = t - (z - 12582912.0f);
    float p =            1.3333558e-3f;
    p = fmaf(p, f, 9.6181291e-3f);
    p = fmaf(p, f, 5.5504110e-2f);
    p = fmaf(p, f, 2.4022651e-1f);
    p = fmaf(p, f, 6.9314718e-1f);
    p = fmaf(p, f, 1.0f);
    return __int_as_float(__float_as_int(p) + ni);
}

__device__ __forceinline__ void split_store4(__nv_bfloat16* hp, __nv_bfloat16* lp,
                                             float v0, float v1, float v2, float v3)
{
    __nv_bfloat16 h0 = __float2bfloat16(v0), h1 = __float2bfloat16(v1);
    __nv_bfloat16 h2 = __float2bfloat16(v2), h3 = __float2bfloat16(v3);
    *(__nv_bfloat162*)(hp)     = __halves2bfloat162(h0, h1);
    *(__nv_bfloat162*)(hp + 2) = __halves2bfloat162(h2, h3);
    *(__nv_bfloat162*)(lp)     = __halves2bfloat162(
        __float2bfloat16(v0 - __bfloat162float(h0)),
        __float2bfloat16(v1 - __bfloat162float(h1)));
    *(__nv_bfloat162*)(lp + 2) = __halves2bfloat162(
        __float2bfloat16(v2 - __bfloat162float(h2)),
        __float2bfloat16(v3 - __bfloat162float(h3)));
}

// ---------------- init ----------------
__global__ void init_kernel() {
    if (threadIdx.x == 0 && blockIdx.x == 0) g_msum = 0;
}

// ---------------- convert x -> hi/lo bf16 ----------------
__global__ void convx_kernel(const float* __restrict__ x) {
    int i = blockIdx.x * blockDim.x + threadIdx.x;
    float4 v = ((const float4*)x)[i];
    split_store4(g_x_hi + (size_t)i * 4, g_x_lo + (size_t)i * 4,
                 v.x, v.y, v.z, v.w);
}

// ---------------- transpose+convert W -> W^T splits ----------------
// z<3: bf16 hi/lo.  z==3 (Wo): fp16 hi/lo.
__global__ void convw_kernel(const float* __restrict__ Wq,
                             const float* __restrict__ Wk,
                             const float* __restrict__ Wv,
                             const float* __restrict__ Wo)
{
    __shared__ float tile[32][33];
    const int z = blockIdx.z;
    const float* W = (z == 0) ? Wq : (z == 1) ? Wk : (z == 2) ? Wv : Wo;
    const int tx = threadIdx.x, ty = threadIdx.y;
    const int bk = blockIdx.y * 32, bn = blockIdx.x * 32;
    #pragma unroll
    for (int r = 0; r < 4; r++)
        tile[ty + 8*r][tx] = W[(size_t)(bk + ty + 8*r) * 512 + bn + tx];
    __syncthreads();
    #pragma unroll
    for (int r = 0; r < 4; r++) {
        int n = bn + ty + 8*r, k = bk + tx;
        float v = tile[tx][ty + 8*r];
        size_t o = (size_t)n * 512 + k;
        if (z < 3) {
            __nv_bfloat16 h = __float2bfloat16(v);
            g_wt_hi[(size_t)z * 262144 + o] = h;
            g_wt_lo[(size_t)z * 262144 + o] =
                __float2bfloat16(v - __bfloat162float(h));
        } else {
            __half h = __float2half_rn(v);
            g_wo_hi[o] = h;
            g_wo_lo[o] = __float2half_rn(v - __half2float(h));
        }
    }
}

// ================= HMMA QKV GEMM, 128x64 tile, occ 2 =================
#define SA_HI 0
#define SA_LO 16384
#define SB_HI 32768
#define SB_LO 40960
#define STAGE_B 49152
#define BMMA_SMEM (2*STAGE_B)

__global__ __launch_bounds__(256, 2)
void bmma_kernel(const float* __restrict__ b0, const float* __restrict__ b1,
                 const float* __restrict__ b2)
{
    extern __shared__ char smc[];
    const uint32_t smb = smem_to_u32(smc);
    const int tid = threadIdx.x;
    const int wid = tid >> 5, lane = tid & 31;
    const int z = blockIdx.z;
    const int bm = blockIdx.y * 128, bn = blockIdx.x * 64;

    const __nv_bfloat16* Ah = g_x_hi;
    const __nv_bfloat16* Al = g_x_lo;
    const __nv_bfloat16* Bh = g_wt_hi + (size_t)z * 262144;
    const __nv_bfloat16* Bl = g_wt_lo + (size_t)z * 262144;
    const float* bias = (z == 0) ? b0 : (z == 1) ? b1 : b2;

    float acc[8][4] = {};
    const int ldr = tid >> 3, ldu = tid & 7;

    auto issue = [&](int kc, int st) {
        const uint32_t sb = smb + st * STAGE_B;
        #pragma unroll
        for (int it = 0; it < 4; it++) {
            int r = ldr + it * 32;
            size_t ga = (size_t)(bm + r) * 512 + kc * 64 + ldu * 8;
            uint32_t so = SMEM_SWZ((uint32_t)(r * 128 + ldu * 16));
            CP_ASYNC16(sb + SA_HI + so, Ah + ga);
            CP_ASYNC16(sb + SA_LO + so, Al + ga);
        }
        #pragma unroll
        for (int it = 0; it < 2; it++) {
            int r = ldr + it * 32;
            size_t gb = (size_t)(bn + r) * 512 + kc * 64 + ldu * 8;
            uint32_t so = SMEM_SWZ((uint32_t)(r * 128 + ldu * 16));
            CP_ASYNC16(sb + SB_HI + so, Bh + gb);
            CP_ASYNC16(sb + SB_LO + so, Bl + gb);
        }
        CP_COMMIT();
    };

    issue(0, 0);
    for (int kc = 0; kc < 8; kc++) {
        const int st = kc & 1;
        const uint32_t sb = smb + st * STAGE_B;
        if (kc < 7) { issue(kc + 1, st ^ 1); CP_WAIT1(); }
        else        { CP_WAIT0(); }
        __syncthreads();

        #pragma unroll
        for (int ks = 0; ks < 4; ks++) {
            uint32_t ah[4], al[4], bhf[8][2], blf[8][2];
            const int arow = wid * 16 + (lane & 15);
            const int akb  = ks * 32 + (lane >> 4) * 16;
            {
                uint32_t off = SMEM_SWZ((uint32_t)(arow * 128 + akb));
                LDSM4(ah[0], ah[1], ah[2], ah[3], sb + SA_HI + off);
                LDSM4(al[0], al[1], al[2], al[3], sb + SA_LO + off);
            }
            const int lr = lane & 7, sel = lane >> 3;
            const int nrow = ((sel >> 1) & 1) * 8 + lr;
            const int bkb  = ks * 32 + (sel & 1) * 16;
            #pragma unroll
            for (int p = 0; p < 4; p++) {
                uint32_t off = SMEM_SWZ((uint32_t)((nrow + p * 16) * 128 + bkb));
                LDSM4(bhf[2*p][0], bhf[2*p][1], bhf[2*p+1][0], bhf[2*p+1][1],
                      sb + SB_HI + off);
                LDSM4(blf[2*p][0], blf[2*p][1], blf[2*p+1][0], blf[2*p+1][1],
                      sb + SB_LO + off);
            }
            #pragma unroll
            for (int nb = 0; nb < 8; nb++) {
                MMA16816(acc[nb], ah, bhf[nb][0], bhf[nb][1]);
                MMA16816(acc[nb], ah, blf[nb][0], blf[nb][1]);
                MMA16816(acc[nb], al, bhf[nb][0], bhf[nb][1]);
            }
        }
        __syncthreads();
    }

    // ---------------- epilogue ----------------
    const int g = lane >> 2, t = lane & 3;
    const int h = bn >> 6;
    float2 bv[8];
    #pragma unroll
    for (int nb = 0; nb < 8; nb++)
        bv[nb] = *(const float2*)&bias[bn + nb * 8 + 2 * t];

    #pragma unroll
    for (int half = 0; half < 2; half++) {
        const int rglob = bm + wid * 16 + g + half * 8;
        const int bi = rglob >> 10, n = rglob & 1023;
        float ss = 0.f;
        #pragma unroll
        for (int nb = 0; nb < 8; nb++) {
            float v0 = acc[nb][half * 2 + 0] + bv[nb].x;
            float v1 = acc[nb][half * 2 + 1] + bv[nb].y;
            ss += v0 * v0 + v1 * v1;
            const int d = nb * 8 + 2 * t;
            if (z == 2) {
                size_t vb = ((size_t)(bi*HH + h)*DHD + d)*NN + n;
                g_vt_h[vb]      = __float2half_rn(v0);
                g_vt_h[vb + NN] = __float2half_rn(v1);
            } else {
                __nv_bfloat16 h0 = __float2bfloat16(v0);
                __nv_bfloat16 h1 = __float2bfloat16(v1);
                __nv_bfloat16 l0 = __float2bfloat16(v0 - __bfloat162float(h0));
                __nv_bfloat16 l1 = __float2bfloat16(v1 - __bfloat162float(h1));
                __nv_bfloat16* dh = (z == 0) ? g_q_hi : g_k_hi;
                __nv_bfloat16* dl = (z == 0) ? g_q_lo : g_k_lo;
                size_t qb = ((size_t)(bi*HH + h)*NN + n)*DHD + d;
                *(__nv_bfloat162*)(dh + qb) = __halves2bfloat162(h0, h1);
                *(__nv_bfloat162*)(dl + qb) = __halves2bfloat162(l0, l1);
            }
        }
        if (z < 2) {
            ss += __shfl_xor_sync(0xffffffffu, ss, 1);
            ss += __shfl_xor_sync(0xffffffffu, ss, 2);
            if (t == 0) {
                float* dst = (z == 0) ? g_qni : g_kni;
                dst[(bi * HH + h) * NN + n] = rsqrtf(ss);
            }
        }
    }
}

// ================= out projection: fp16 ctx @ fp16-split Wo, occ 2 =========
#define OSA    0
#define OSB_HI 16384
#define OSB_LO 24576
#define OSTAGE 32768
#define OPROJ_SMEM (2*OSTAGE)

__global__ __launch_bounds__(256, 2)
void outproj2_kernel(const float* __restrict__ bias, float* __restrict__ out)
{
    extern __shared__ char smc[];
    const uint32_t smb = smem_to_u32(smc);
    const int tid = threadIdx.x;
    const int wid = tid >> 5, lane = tid & 31;
    const int bm = blockIdx.y * 128, bn = blockIdx.x * 64;

    float acc[8][4] = {};
    const int ldr = tid >> 3, ldu = tid & 7;

    auto issue = [&](int kc, int st) {
        const uint32_t sb = smb + st * OSTAGE;
        #pragma unroll
        for (int it = 0; it < 4; it++) {          // A: 128 rows fp16
            int r = ldr + it * 32;
            size_t ga = (size_t)(bm + r) * 512 + kc * 64 + ldu * 8;
            uint32_t so = SMEM_SWZ((uint32_t)(r * 128 + ldu * 16));
            CP_ASYNC16(sb + OSA + so, g_ctx_h + ga);
        }
        #pragma unroll
        for (int it = 0; it < 2; it++) {          // B: 64 rows hi+lo
            int r = ldr + it * 32;
            size_t gb = (size_t)(bn + r) * 512 + kc * 64 + ldu * 8;
            uint32_t so = SMEM_SWZ((uint32_t)(r * 128 + ldu * 16));
            CP_ASYNC16(sb + OSB_HI + so, g_wo_hi + gb);
            CP_ASYNC16(sb + OSB_LO + so, g_wo_lo + gb);
        }
        CP_COMMIT();
    };

    issue(0, 0);
    for (int kc = 0; kc < 8; kc++) {
        const int st = kc & 1;
        const uint32_t sb = smb + st * OSTAGE;
        if (kc < 7) { issue(kc + 1, st ^ 1); CP_WAIT1(); }
        else        { CP_WAIT0(); }
        __syncthreads();

        #pragma unroll
        for (int ks = 0; ks < 4; ks++) {
            uint32_t ah[4], bhf[8][2], blf[8][2];
            const int arow = wid * 16 + (lane & 15);
            const int akb  = ks * 32 + (lane >> 4) * 16;
            {
                uint32_t off = SMEM_SWZ((uint32_t)(arow * 128 + akb));
                LDSM4(ah[0], ah[1], ah[2], ah[3], sb + OSA + off);
            }
            const int lr = lane & 7, sel = lane >> 3;
            const int nrow = ((sel >> 1) & 1) * 8 + lr;
            const int bkb  = ks * 32 + (sel & 1) * 16;
            #pragma unroll
            for (int p = 0; p < 4; p++) {
                uint32_t off = SMEM_SWZ((uint32_t)((nrow + p * 16) * 128 + bkb));
                LDSM4(bhf[2*p][0], bhf[2*p][1], bhf[2*p+1][0], bhf[2*p+1][1],
                      sb + OSB_HI + off);
                LDSM4(blf[2*p][0], blf[2*p][1], blf[2*p+1][0], blf[2*p+1][1],
                      sb + OSB_LO + off);
            }
            #pragma unroll
            for (int nb = 0; nb < 8; nb++) {
                MMA16816H(acc[nb], ah, bhf[nb][0], bhf[nb][1]);
                MMA16816H(acc[nb], ah, blf[nb][0], blf[nb][1]);
            }
        }
        __syncthreads();
    }

    const int g = lane >> 2, t = lane & 3;
    float2 bv[8];
    #pragma unroll
    for (int nb = 0; nb < 8; nb++)
        bv[nb] = *(const float2*)&bias[bn + nb * 8 + 2 * t];

    #pragma unroll
    for (int half = 0; half < 2; half++) {
        const int rglob = bm + wid * 16 + g + half * 8;
        #pragma unroll
        for (int nb = 0; nb < 8; nb++) {
            float v0 = acc[nb][half * 2 + 0] + bv[nb].x;
            float v1 = acc[nb][half * 2 + 1] + bv[nb].y;
            *(float2*)(out + (size_t)rglob * 512 + bn + nb * 8 + 2 * t) =
                make_float2(v0, v1);
        }
    }
}

// ============ fused attention, occ=2 (round-12 structure) ============
#define ES_B 2064
#define KT_B 144
#define VT_B 272
#define STG_LO2 9216
#define OFF_ES  0
#define OFF_ST0 66048
#define OFF_ST1 84480
#define OFF_RED 102912
#define OFF_INVS 105984
#define OFF_WCNT 106112
#define ATTN_SMEM 106496

__global__ __launch_bounds__(256, 2)
void attn4_kernel(const int* __restrict__ mask, float* __restrict__ attn_out)
{
    extern __shared__ char smc[];
    const uint32_t smb = smem_to_u32(smc);
    float* invs = (float*)(smc + OFF_INVS);
    float* red  = (float*)(smc + OFF_RED);
    int*   wcnt = (int*)(smc + OFF_WCNT);

    const int tid  = threadIdx.x;
    const int warp = tid >> 5, lane = tid & 31;
    const int g = lane >> 2, t = lane & 3;
    const int lr = lane & 7, sel = lane >> 3;
    const int blk = blockIdx.x;             // 1024
    const int bh  = blk >> 5;
    const int i0  = (blk & 31) * 32;
    const int b   = bh >> 3;

    const uint32_t stg[2] = {smb + OFF_ST0, smb + OFF_ST1};

    auto issueK = [&](int jt, uint32_t sb) {
        #pragma unroll
        for (int it = 0; it < 2; it++) {
            int idx = tid + it * 256;
            int r = idx >> 3, u = idx & 7;
            size_t gk = ((size_t)(bh * NN + jt * 64 + r)) * DHD + u * 8;
            CP_ASYNC16(sb + r * KT_B + u * 16, g_k_hi + gk);
            CP_ASYNC16(sb + STG_LO2 + r * KT_B + u * 16, g_k_lo + gk);
        }
        CP_COMMIT();
    };
    auto issueV = [&](int jt, uint32_t sb) {
        #pragma unroll
        for (int it = 0; it < 4; it++) {
            int idx = tid + it * 256;
            int d = idx >> 4, u = idx & 15;
            size_t gv = ((size_t)bh * DHD + d) * NN + jt * 128 + u * 8;
            CP_ASYNC16(sb + d * VT_B + u * 16, g_vt_h + gv);
        }
        CP_COMMIT();
    };

    issueK(0, stg[0]);
    {
        int r = tid >> 3, u = tid & 7;
        size_t gq = ((size_t)(bh * NN + i0 + r)) * DHD + u * 8;
        *(uint4*)(smc + OFF_ST1 + r * KT_B + u * 16) = *(const uint4*)(g_q_hi + gq);
        *(uint4*)(smc + OFF_ST1 + 4608 + r * KT_B + u * 16) = *(const uint4*)(g_q_lo + gq);
    }
    __syncthreads();
    uint32_t qh[2][4][4], ql[2][4][4];
    #pragma unroll
    for (int m = 0; m < 2; m++)
        #pragma unroll
        for (int ks = 0; ks < 4; ks++) {
            uint32_t a = smb + OFF_ST1 + (m * 16 + (lane & 15)) * KT_B
                       + ks * 32 + (lane >> 4) * 16;
            LDSM4(qh[m][ks][0], qh[m][ks][1], qh[m][ks][2], qh[m][ks][3], a);
            LDSM4(ql[m][ks][0], ql[m][ks][1], ql[m][ks][2], ql[m][ks][3], a + 4608);
        }
    __syncthreads();
    issueK(1, stg[1]);

    float qn10[2][2];
    #pragma unroll
    for (int m = 0; m < 2; m++)
        #pragma unroll
        for (int hf = 0; hf < 2; hf++)
            qn10[m][hf] = g_qni[bh * NN + i0 + m * 16 + g + hf * 8] * 10.0f;

    float rall[2][2] = {}, rpos[2][2] = {}, rsum[2][2] = {};
    int cnt = 0;

    for (int jt = 0; jt < 16; jt++) {
        if (jt < 15) CP_WAIT1(); else CP_WAIT0();
        __syncthreads();
        const uint32_t sb = stg[jt & 1];

        float acc[2][4] = {};
        #pragma unroll
        for (int kp = 0; kp < 2; kp++) {
            uint32_t kh4[4], kl4[4];
            uint32_t ka = sb + (warp * 8 + lr) * KT_B + kp * 64 + sel * 16;
            LDSM4(kh4[0], kh4[1], kh4[2], kh4[3], ka);
            LDSM4(kl4[0], kl4[1], kl4[2], kl4[3], ka + STG_LO2);
            #pragma unroll
            for (int h2 = 0; h2 < 2; h2++) {
                const int ks = kp * 2 + h2;
                #pragma unroll
                for (int m = 0; m < 2; m++) {
                    MMA16816(acc[m], qh[m][ks], kh4[h2*2], kh4[h2*2+1]);
                    MMA16816(acc[m], qh[m][ks], kl4[h2*2], kl4[h2*2+1]);
                    MMA16816(acc[m], ql[m][ks], kh4[h2*2], kh4[h2*2+1]);
                }
            }
        }

        const int j0 = jt * 64 + warp * 8 + t * 2;
        float2 kn = *(const float2*)&g_kni[bh * NN + j0];
        #pragma unroll
        for (int m = 0; m < 2; m++)
            #pragma unroll
            for (int hf = 0; hf < 2; hf++) {
                const int il = m * 16 + g + hf * 8;
                int2 mm = *(const int2*)(mask +
                          ((size_t)(b * NN + i0 + il)) * NN + j0);
                float d0 = acc[m][hf * 2 + 0];
                float d1 = acc[m][hf * 2 + 1];
                float qn = qn10[m][hf];
                float ec0 = fexp(d0 * qn * kn.x);
                float ec1 = fexp(d1 * qn * kn.y);
                rall[m][hf] += ec0 + ec1;
                rpos[m][hf] += (mm.x ? ec0 : 0.f) + (mm.y ? ec1 : 0.f);
                cnt += (mm.x != 0) + (mm.y != 0);
                float es0 = mm.x ? fexp(d0 * SCALE) : 0.f;
                float es1 = mm.y ? fexp(d1 * SCALE) : 0.f;
                rsum[m][hf] += es0 + es1;
                *(__half2*)(smc + OFF_ES + il * ES_B + j0 * 2) =
                    __floats2half2_rn(es0, es1);
            }
        __syncthreads();
        if (jt + 2 <= 15) issueK(jt + 2, stg[jt & 1]);
    }

    #pragma unroll
    for (int m = 0; m < 2; m++)
        #pragma unroll
        for (int hf = 0; hf < 2; hf++) {
            #pragma unroll
            for (int o = 1; o <= 2; o <<= 1) {
                rall[m][hf] += __shfl_xor_sync(0xffffffffu, rall[m][hf], o);
                rpos[m][hf] += __shfl_xor_sync(0xffffffffu, rpos[m][hf], o);
                rsum[m][hf] += __shfl_xor_sync(0xffffffffu, rsum[m][hf], o);
            }
        }
    #pragma unroll
    for (int o = 16; o > 0; o >>= 1)
        cnt += __shfl_xor_sync(0xffffffffu, cnt, o);
    if (t == 0) {
        #pragma unroll
        for (int m = 0; m < 2; m++)
            #pragma unroll
            for (int hf = 0; hf < 2; hf++) {
                int il = m * 16 + g + hf * 8;
                red[(warp * 32 + il) * 3 + 0] = rall[m][hf];
                red[(warp * 32 + il) * 3 + 1] = rpos[m][hf];
                red[(warp * 32 + il) * 3 + 2] = rsum[m][hf];
            }
    }
    if (lane == 0) wcnt[warp] = cnt;
    __syncthreads();
    if (tid < 32) {
        float a = 0.f, p = 0.f, s = 0.f;
        #pragma unroll
        for (int w = 0; w < 8; w++) {
            a += red[(w * 32 + tid) * 3 + 0];
            p += red[(w * 32 + tid) * 3 + 1];
            s += red[(w * 32 + tid) * 3 + 2];
        }
        invs[tid] = __frcp_rn(s);
        g_clus[bh * NN + i0 + tid] = -__logf(__fdividef(p, a));
    }
    if (tid == 32) {
        int s = 0;
        #pragma unroll
        for (int w = 0; w < 8; w++) s += wcnt[w];
        atomicAdd(&g_msum, s);
    }
    __syncthreads();

    issueV(0, stg[0]);
    issueV(1, stg[1]);

    #pragma unroll 4
    for (int it = 0; it < 16; it++) {
        int idx = tid + it * 256;
        int row = idx >> 7, u = idx & 127;
        uint4 vh = *(const uint4*)(smc + OFF_ES + row * ES_B + u * 16);
        float s = invs[row];
        const __half2* ph = (const __half2*)&vh;
        float ov[8];
        #pragma unroll
        for (int p2 = 0; p2 < 4; p2++) {
            float2 f = __half22float2(ph[p2]);
            ov[2*p2+0] = f.x * s;
            ov[2*p2+1] = f.y * s;
        }
        float* dst = attn_out + ((size_t)bh * NN + i0 + row) * NN + u * 8;
        *(float4*)dst       = make_float4(ov[0], ov[1], ov[2], ov[3]);
        *(float4*)(dst + 4) = make_float4(ov[4], ov[5], ov[6], ov[7]);
    }

    const int wm = warp >> 2, wd = warp & 3;
    float acc2[2][4] = {};

    for (int jt = 0; jt < 8; jt++) {
        if (jt < 7) CP_WAIT1(); else CP_WAIT0();
        __syncthreads();
        const uint32_t sb = stg[jt & 1];

        #pragma unroll
        for (int ks2 = 0; ks2 < 8; ks2++) {
            uint32_t ah[4], vh4[4];
            uint32_t aa = smb + OFF_ES + (wm * 16 + (lane & 15)) * ES_B
                        + jt * 256 + ks2 * 32 + (lane >> 4) * 16;
            LDSM4(ah[0], ah[1], ah[2], ah[3], aa);
            uint32_t va = sb + (wd * 16 + ((sel >> 1) & 1) * 8 + lr) * VT_B
                        + ks2 * 32 + (sel & 1) * 16;
            LDSM4(vh4[0], vh4[1], vh4[2], vh4[3], va);
            #pragma unroll
            for (int nb = 0; nb < 2; nb++)
                MMA16816H(acc2[nb], ah, vh4[nb*2], vh4[nb*2+1]);
        }
        __syncthreads();
        if (jt + 2 <= 7) issueV(jt + 2, stg[jt & 1]);
    }

    const int h = bh & 7;
    #pragma unroll
    for (int nb = 0; nb < 2; nb++)
        #pragma unroll
        for (int hf = 0; hf < 2; hf++) {
            int i = wm * 16 + g + hf * 8;
            int d = wd * 16 + nb * 8 + t * 2;
            float s = invs[i];
            float v0 = acc2[nb][hf * 2 + 0] * s;
            float v1 = acc2[nb][hf * 2 + 1] * s;
            size_t base = ((size_t)(b * NN + i0 + i)) * INNERD + h * DHD + d;
            *(__half2*)(g_ctx_h + base) = __floats2half2_rn(v0, v1);
        }
}

// ---------------- final dcl scalar ----------------
__global__ void dcl_kernel(float* out_dcl) {
    __shared__ float red[1024];
    const int tid = threadIdx.x;
    float s = 0.f;
    const int base = tid * 32;
    #pragma unroll 8
    for (int i = 0; i < 32; i++) s += g_clus[base + i];
    red[tid] = s;
    __syncthreads();
    for (int o = 512; o > 0; o >>= 1) {
        if (tid < o) red[tid] += red[tid + o];
        __syncthreads();
    }
    if (tid == 0 && out_dcl) {
        float clus_mean = red[0] / (float)NROWS;
        float regular = ((float)(g_msum >> 3) - (float)(BB * NN)) /
                        ((float)BB * (float)NN * (float)(NN - 1));
        out_dcl[0] = clus_mean + 0.3f * regular;
    }
}

// ---------------- launcher ----------------
extern "C" void kernel_launch(void* const* d_in, const int* in_sizes, int n_in,
                              void* d_out, int out_size) {
    const float* x   = (const float*)d_in[0];
    const int*   msk = (const int*)  d_in[1];
    const float* Wq  = (const float*)d_in[2];
    const float* bq  = (const float*)d_in[3];
    const float* Wk  = (const float*)d_in[4];
    const float* bk  = (const float*)d_in[5];
    const float* Wv  = (const float*)d_in[6];
    const float* bv  = (const float*)d_in[7];
    const float* Wo  = (const float*)d_in[8];
    const float* bo  = (const float*)d_in[9];
    float* out = (float*)d_out;

    const size_t OUTE  = (size_t)BB * NN * DIMD;
    const size_t ATTNE = (size_t)BH * NN * NN;

    float* attn_ptr;
    if ((size_t)out_size >= OUTE + ATTNE) {
        attn_ptr = out + OUTE;
    } else {
        void* p = nullptr;
        cudaGetSymbolAddress(&p, g_attn_fb);
        attn_ptr = (float*)p;
    }
    float* dcl_ptr = ((size_t)out_size >= OUTE + ATTNE + 1) ? (out + OUTE + ATTNE)
                                                            : nullptr;

    cudaFuncSetAttribute(attn4_kernel,
                         cudaFuncAttributeMaxDynamicSharedMemorySize, ATTN_SMEM);
    cudaFuncSetAttribute(bmma_kernel,
                         cudaFuncAttributeMaxDynamicSharedMemorySize, BMMA_SMEM);
    cudaFuncSetAttribute(outproj2_kernel,
                         cudaFuncAttributeMaxDynamicSharedMemorySize, OPROJ_SMEM);

    init_kernel<<<1, 32>>>();
    convx_kernel<<<2048, 256>>>(x);
    convw_kernel<<<dim3(16, 16, 4), dim3(32, 8)>>>(Wq, Wk, Wv, Wo);

    dim3 qkvgrid(DIMD / 64, (BB * NN) / 128, 3);   // (8, 32, 3)
    bmma_kernel<<<qkvgrid, 256, BMMA_SMEM>>>(bq, bk, bv);

    attn4_kernel<<<BH * (NN / 32), 256, ATTN_SMEM>>>(msk, attn_ptr);

    dim3 ogrid(DIMD / 64, (BB * NN) / 128);        // (8, 32)
    outproj2_kernel<<<ogrid, 256, OPROJ_SMEM>>>(bo, out);

    dcl_kernel<<<1, 1024>>>(dcl_ptr);
}

// round 15
// speedup vs baseline: 1.2414x; 1.1676x over previous
#include <cuda_runtime.h>
#include <cuda_bf16.h>
#include <cuda_fp16.h>
#include <math.h>
#include <stdint.h>

#define BB 4
#define NN 1024
#define DIMD 512
#define HH 8
#define DHD 64
#define INNERD 512
#define BH (BB*HH)            // 32
#define NROWS (BH*NN)         // 32768
#define SCALE 0.125f

// ---------------- scratch (device globals; no runtime allocation) ----------
__device__ float g_qni[NROWS];              // reciprocal q norms
__device__ float g_kni[NROWS];              // reciprocal k norms
__device__ float g_clus[NROWS];
__device__ int   g_msum;                    // 8 * sum(mask)
__device__ float g_attn_fb[(size_t)BH*NN*NN];
// split operands
__device__ __nv_bfloat16 g_x_hi[(size_t)BB*NN*DIMD];
__device__ __nv_bfloat16 g_x_lo[(size_t)BB*NN*DIMD];
__device__ __nv_bfloat16 g_wt_hi[3*512*512];   // W^T [n][k], slots q,k,v
__device__ __nv_bfloat16 g_wt_lo[3*512*512];
__device__ __half        g_wo_hi[512*512];     // Wo^T fp16 hi
__device__ __half        g_wo_lo[512*512];     // Wo^T fp16 lo
__device__ __half        g_ctx_h[(size_t)BB*NN*INNERD];   // fp16 ctx
__device__ __half        g_q_h[NROWS*DHD];     // fp16 [bh][n][d]
__device__ __half        g_k_h[NROWS*DHD];     // fp16 [bh][n][d]
__device__ __half        g_vt_h[NROWS*DHD];    // fp16 TRANSPOSED [bh][d][n]

// ---------------- helpers ----------------
__device__ __forceinline__ uint32_t smem_to_u32(const void* p) {
    uint32_t a;
    asm("{ .reg .u64 t; cvta.to.shared.u64 t, %1; cvt.u32.u64 %0, t; }"
        : "=r"(a) : "l"(p));
    return a;
}
#define SMEM_SWZ(off) ((off) ^ (((off) >> 3) & 0x70))

#define LDSM4(R0, R1, R2, R3, ADDR) \
    asm volatile("ldmatrix.sync.aligned.m8n8.x4.shared.b16 {%0,%1,%2,%3}, [%4];" \
        : "=r"(R0), "=r"(R1), "=r"(R2), "=r"(R3) : "r"(ADDR))

#define MMA16816(C, A, B0, B1) \
    asm volatile("mma.sync.aligned.m16n8k16.row.col.f32.bf16.bf16.f32 " \
        "{%0,%1,%2,%3}, {%4,%5,%6,%7}, {%8,%9}, {%0,%1,%2,%3};" \
        : "+f"((C)[0]), "+f"((C)[1]), "+f"((C)[2]), "+f"((C)[3]) \
        : "r"((A)[0]), "r"((A)[1]), "r"((A)[2]), "r"((A)[3]), "r"(B0), "r"(B1))

#define MMA16816H(C, A, B0, B1) \
    asm volatile("mma.sync.aligned.m16n8k16.row.col.f32.f16.f16.f32 " \
        "{%0,%1,%2,%3}, {%4,%5,%6,%7}, {%8,%9}, {%0,%1,%2,%3};" \
        : "+f"((C)[0]), "+f"((C)[1]), "+f"((C)[2]), "+f"((C)[3]) \
        : "r"((A)[0]), "r"((A)[1]), "r"((A)[2]), "r"((A)[3]), "r"(B0), "r"(B1))

#define CP_ASYNC16(smaddr, gptr) \
    asm volatile("cp.async.cg.shared.global [%0], [%1], 16;" \
        :: "r"(smaddr), "l"(gptr) : "memory")
#define CP_COMMIT() asm volatile("cp.async.commit_group;" ::: "memory")
#define CP_WAIT1() asm volatile("cp.async.wait_group 1;" ::: "memory")
#define CP_WAIT0() asm volatile("cp.async.wait_group 0;" ::: "memory")

// FMA-pipe exp (no MUFU)
__device__ __forceinline__ float fexp(float x) {
    float t = x * 1.4426950408889634f;
    float z = t + 12582912.0f;
    int ni = __float_as_int(z) << 23;
    float f = t - (z - 12582912.0f);
    float p =            1.3333558e-3f;
    p = fmaf(p, f, 9.6181291e-3f);
    p = fmaf(p, f, 5.5504110e-2f);
    p = fmaf(p, f, 2.4022651e-1f);
    p = fmaf(p, f, 6.9314718e-1f);
    p = fmaf(p, f, 1.0f);
    return __int_as_float(__float_as_int(p) + ni);
}

__device__ __forceinline__ void split_store4(__nv_bfloat16* hp, __nv_bfloat16* lp,
                                             float v0, float v1, float v2, float v3)
{
    __nv_bfloat16 h0 = __float2bfloat16(v0), h1 = __float2bfloat16(v1);
    __nv_bfloat16 h2 = __float2bfloat16(v2), h3 = __float2bfloat16(v3);
    *(__nv_bfloat162*)(hp)     = __halves2bfloat162(h0, h1);
    *(__nv_bfloat162*)(hp + 2) = __halves2bfloat162(h2, h3);
    *(__nv_bfloat162*)(lp)     = __halves2bfloat162(
        __float2bfloat16(v0 - __bfloat162float(h0)),
        __float2bfloat16(v1 - __bfloat162float(h1)));
    *(__nv_bfloat162*)(lp + 2) = __halves2bfloat162(
        __float2bfloat16(v2 - __bfloat162float(h2)),
        __float2bfloat16(v3 - __bfloat162float(h3)));
}

// ---------------- init ----------------
__global__ void init_kernel() {
    if (threadIdx.x == 0 && blockIdx.x == 0) g_msum = 0;
}

// ---------------- convert x -> hi/lo bf16 ----------------
__global__ void convx_kernel(const float* __restrict__ x) {
    int i = blockIdx.x * blockDim.x + threadIdx.x;
    float4 v = ((const float4*)x)[i];
    split_store4(g_x_hi + (size_t)i * 4, g_x_lo + (size_t)i * 4,
                 v.x, v.y, v.z, v.w);
}

// ---------------- transpose+convert W -> W^T splits ----------------
__global__ void convw_kernel(const float* __restrict__ Wq,
                             const float* __restrict__ Wk,
                             const float* __restrict__ Wv,
                             const float* __restrict__ Wo)
{
    __shared__ float tile[32][33];
    const int z = blockIdx.z;
    const float* W = (z == 0) ? Wq : (z == 1) ? Wk : (z == 2) ? Wv : Wo;
    const int tx = threadIdx.x, ty = threadIdx.y;
    const int bk = blockIdx.y * 32, bn = blockIdx.x * 32;
    #pragma unroll
    for (int r = 0; r < 4; r++)
        tile[ty + 8*r][tx] = W[(size_t)(bk + ty + 8*r) * 512 + bn + tx];
    __syncthreads();
    #pragma unroll
    for (int r = 0; r < 4; r++) {
        int n = bn + ty + 8*r, k = bk + tx;
        float v = tile[tx][ty + 8*r];
        size_t o = (size_t)n * 512 + k;
        if (z < 3) {
            __nv_bfloat16 h = __float2bfloat16(v);
            g_wt_hi[(size_t)z * 262144 + o] = h;
            g_wt_lo[(size_t)z * 262144 + o] =
                __float2bfloat16(v - __bfloat162float(h));
        } else {
            __half h = __float2half_rn(v);
            g_wo_hi[o] = h;
            g_wo_lo[o] = __float2half_rn(v - __half2float(h));
        }
    }
}

// ================= HMMA QKV GEMM, 128x64 tile, occ 2 =================
#define SA_HI 0
#define SA_LO 16384
#define SB_HI 32768
#define SB_LO 40960
#define STAGE_B 49152
#define BMMA_SMEM (2*STAGE_B)

__global__ __launch_bounds__(256, 2)
void bmma_kernel(const float* __restrict__ b0, const float* __restrict__ b1,
                 const float* __restrict__ b2)
{
    extern __shared__ char smc[];
    const uint32_t smb = smem_to_u32(smc);
    const int tid = threadIdx.x;
    const int wid = tid >> 5, lane = tid & 31;
    const int z = blockIdx.z;
    const int bm = blockIdx.y * 128, bn = blockIdx.x * 64;

    const __nv_bfloat16* Ah = g_x_hi;
    const __nv_bfloat16* Al = g_x_lo;
    const __nv_bfloat16* Bh = g_wt_hi + (size_t)z * 262144;
    const __nv_bfloat16* Bl = g_wt_lo + (size_t)z * 262144;
    const float* bias = (z == 0) ? b0 : (z == 1) ? b1 : b2;

    float acc[8][4] = {};
    const int ldr = tid >> 3, ldu = tid & 7;

    auto issue = [&](int kc, int st) {
        const uint32_t sb = smb + st * STAGE_B;
        #pragma unroll
        for (int it = 0; it < 4; it++) {
            int r = ldr + it * 32;
            size_t ga = (size_t)(bm + r) * 512 + kc * 64 + ldu * 8;
            uint32_t so = SMEM_SWZ((uint32_t)(r * 128 + ldu * 16));
            CP_ASYNC16(sb + SA_HI + so, Ah + ga);
            CP_ASYNC16(sb + SA_LO + so, Al + ga);
        }
        #pragma unroll
        for (int it = 0; it < 2; it++) {
            int r = ldr + it * 32;
            size_t gb = (size_t)(bn + r) * 512 + kc * 64 + ldu * 8;
            uint32_t so = SMEM_SWZ((uint32_t)(r * 128 + ldu * 16));
            CP_ASYNC16(sb + SB_HI + so, Bh + gb);
            CP_ASYNC16(sb + SB_LO + so, Bl + gb);
        }
        CP_COMMIT();
    };

    issue(0, 0);
    for (int kc = 0; kc < 8; kc++) {
        const int st = kc & 1;
        const uint32_t sb = smb + st * STAGE_B;
        if (kc < 7) { issue(kc + 1, st ^ 1); CP_WAIT1(); }
        else        { CP_WAIT0(); }
        __syncthreads();

        #pragma unroll
        for (int ks = 0; ks < 4; ks++) {
            uint32_t ah[4], al[4], bhf[8][2], blf[8][2];
            const int arow = wid * 16 + (lane & 15);
            const int akb  = ks * 32 + (lane >> 4) * 16;
            {
                uint32_t off = SMEM_SWZ((uint32_t)(arow * 128 + akb));
                LDSM4(ah[0], ah[1], ah[2], ah[3], sb + SA_HI + off);
                LDSM4(al[0], al[1], al[2], al[3], sb + SA_LO + off);
            }
            const int lr = lane & 7, sel = lane >> 3;
            const int nrow = ((sel >> 1) & 1) * 8 + lr;
            const int bkb  = ks * 32 + (sel & 1) * 16;
            #pragma unroll
            for (int p = 0; p < 4; p++) {
                uint32_t off = SMEM_SWZ((uint32_t)((nrow + p * 16) * 128 + bkb));
                LDSM4(bhf[2*p][0], bhf[2*p][1], bhf[2*p+1][0], bhf[2*p+1][1],
                      sb + SB_HI + off);
                LDSM4(blf[2*p][0], blf[2*p][1], blf[2*p+1][0], blf[2*p+1][1],
                      sb + SB_LO + off);
            }
            #pragma unroll
            for (int nb = 0; nb < 8; nb++) {
                MMA16816(acc[nb], ah, bhf[nb][0], bhf[nb][1]);
                MMA16816(acc[nb], ah, blf[nb][0], blf[nb][1]);
                MMA16816(acc[nb], al, bhf[nb][0], bhf[nb][1]);
            }
        }
        __syncthreads();
    }

    // ---------------- epilogue ----------------
    const int g = lane >> 2, t = lane & 3;
    const int h = bn >> 6;
    float2 bv[8];
    #pragma unroll
    for (int nb = 0; nb < 8; nb++)
        bv[nb] = *(const float2*)&bias[bn + nb * 8 + 2 * t];

    #pragma unroll
    for (int half = 0; half < 2; half++) {
        const int rglob = bm + wid * 16 + g + half * 8;
        const int bi = rglob >> 10, n = rglob & 1023;
        float ss = 0.f;
        #pragma unroll
        for (int nb = 0; nb < 8; nb++) {
            float v0 = acc[nb][half * 2 + 0] + bv[nb].x;
            float v1 = acc[nb][half * 2 + 1] + bv[nb].y;
            ss += v0 * v0 + v1 * v1;
            const int d = nb * 8 + 2 * t;
            if (z == 2) {
                size_t vb = ((size_t)(bi*HH + h)*DHD + d)*NN + n;
                g_vt_h[vb]      = __float2half_rn(v0);
                g_vt_h[vb + NN] = __float2half_rn(v1);
            } else {
                __half* dst = (z == 0) ? g_q_h : g_k_h;
                size_t qb = ((size_t)(bi*HH + h)*NN + n)*DHD + d;
                *(__half2*)(dst + qb) = __floats2half2_rn(v0, v1);
            }
        }
        if (z < 2) {
            ss += __shfl_xor_sync(0xffffffffu, ss, 1);
            ss += __shfl_xor_sync(0xffffffffu, ss, 2);
            if (t == 0) {
                float* dst = (z == 0) ? g_qni : g_kni;
                dst[(bi * HH + h) * NN + n] = rsqrtf(ss);
            }
        }
    }
}

// ================= out projection: fp16 ctx @ fp16-split Wo, occ 2 =========
#define OSA    0
#define OSB_HI 16384
#define OSB_LO 24576
#define OSTAGE 32768
#define OPROJ_SMEM (2*OSTAGE)

__global__ __launch_bounds__(256, 2)
void outproj2_kernel(const float* __restrict__ bias, float* __restrict__ out)
{
    extern __shared__ char smc[];
    const uint32_t smb = smem_to_u32(smc);
    const int tid = threadIdx.x;
    const int wid = tid >> 5, lane = tid & 31;
    const int bm = blockIdx.y * 128, bn = blockIdx.x * 64;

    float acc[8][4] = {};
    const int ldr = tid >> 3, ldu = tid & 7;

    auto issue = [&](int kc, int st) {
        const uint32_t sb = smb + st * OSTAGE;
        #pragma unroll
        for (int it = 0; it < 4; it++) {
            int r = ldr + it * 32;
            size_t ga = (size_t)(bm + r) * 512 + kc * 64 + ldu * 8;
            uint32_t so = SMEM_SWZ((uint32_t)(r * 128 + ldu * 16));
            CP_ASYNC16(sb + OSA + so, g_ctx_h + ga);
        }
        #pragma unroll
        for (int it = 0; it < 2; it++) {
            int r = ldr + it * 32;
            size_t gb = (size_t)(bn + r) * 512 + kc * 64 + ldu * 8;
            uint32_t so = SMEM_SWZ((uint32_t)(r * 128 + ldu * 16));
            CP_ASYNC16(sb + OSB_HI + so, g_wo_hi + gb);
            CP_ASYNC16(sb + OSB_LO + so, g_wo_lo + gb);
        }
        CP_COMMIT();
    };

    issue(0, 0);
    for (int kc = 0; kc < 8; kc++) {
        const int st = kc & 1;
        const uint32_t sb = smb + st * OSTAGE;
        if (kc < 7) { issue(kc + 1, st ^ 1); CP_WAIT1(); }
        else        { CP_WAIT0(); }
        __syncthreads();

        #pragma unroll
        for (int ks = 0; ks < 4; ks++) {
            uint32_t ah[4], bhf[8][2], blf[8][2];
            const int arow = wid * 16 + (lane & 15);
            const int akb  = ks * 32 + (lane >> 4) * 16;
            {
                uint32_t off = SMEM_SWZ((uint32_t)(arow * 128 + akb));
                LDSM4(ah[0], ah[1], ah[2], ah[3], sb + OSA + off);
            }
            const int lr = lane & 7, sel = lane >> 3;
            const int nrow = ((sel >> 1) & 1) * 8 + lr;
            const int bkb  = ks * 32 + (sel & 1) * 16;
            #pragma unroll
            for (int p = 0; p < 4; p++) {
                uint32_t off = SMEM_SWZ((uint32_t)((nrow + p * 16) * 128 + bkb));
                LDSM4(bhf[2*p][0], bhf[2*p][1], bhf[2*p+1][0], bhf[2*p+1][1],
                      sb + OSB_HI + off);
                LDSM4(blf[2*p][0], blf[2*p][1], blf[2*p+1][0], blf[2*p+1][1],
                      sb + OSB_LO + off);
            }
            #pragma unroll
            for (int nb = 0; nb < 8; nb++) {
                MMA16816H(acc[nb], ah, bhf[nb][0], bhf[nb][1]);
                MMA16816H(acc[nb], ah, blf[nb][0], blf[nb][1]);
            }
        }
        __syncthreads();
    }

    const int g = lane >> 2, t = lane & 3;
    float2 bv[8];
    #pragma unroll
    for (int nb = 0; nb < 8; nb++)
        bv[nb] = *(const float2*)&bias[bn + nb * 8 + 2 * t];

    #pragma unroll
    for (int half = 0; half < 2; half++) {
        const int rglob = bm + wid * 16 + g + half * 8;
        #pragma unroll
        for (int nb = 0; nb < 8; nb++) {
            float v0 = acc[nb][half * 2 + 0] + bv[nb].x;
            float v1 = acc[nb][half * 2 + 1] + bv[nb].y;
            *(float2*)(out + (size_t)rglob * 512 + bn + nb * 8 + 2 * t) =
                make_float2(v0, v1);
        }
    }
}

// ============ fused attention, occ=2: single fp16 q/k/es/v ============
#define ES_B 2064
#define KT_B 144
#define VT_B 272
#define OFF_ES  0
#define OFF_ST0 66048
#define OFF_ST1 84480
#define OFF_RED 102912
#define OFF_INVS 105984
#define OFF_WCNT 106112
#define ATTN_SMEM 106496

__global__ __launch_bounds__(256, 2)
void attn5_kernel(const int* __restrict__ mask, float* __restrict__ attn_out)
{
    extern __shared__ char smc[];
    const uint32_t smb = smem_to_u32(smc);
    float* invs = (float*)(smc + OFF_INVS);
    float* red  = (float*)(smc + OFF_RED);
    int*   wcnt = (int*)(smc + OFF_WCNT);

    const int tid  = threadIdx.x;
    const int warp = tid >> 5, lane = tid & 31;
    const int g = lane >> 2, t = lane & 3;
    const int lr = lane & 7, sel = lane >> 3;
    const int blk = blockIdx.x;             // 1024
    const int bh  = blk >> 5;
    const int i0  = (blk & 31) * 32;
    const int b   = bh >> 3;

    const uint32_t stg[2] = {smb + OFF_ST0, smb + OFF_ST1};

    auto issueK = [&](int jt, uint32_t sb) {      // 64 j-rows fp16
        #pragma unroll
        for (int it = 0; it < 2; it++) {
            int idx = tid + it * 256;
            int r = idx >> 3, u = idx & 7;
            size_t gk = ((size_t)(bh * NN + jt * 64 + r)) * DHD + u * 8;
            CP_ASYNC16(sb + r * KT_B + u * 16, g_k_h + gk);
        }
        CP_COMMIT();
    };
    auto issueV = [&](int jt, uint32_t sb) {      // 64 d-rows x 128 j fp16
        #pragma unroll
        for (int it = 0; it < 4; it++) {
            int idx = tid + it * 256;
            int d = idx >> 4, u = idx & 15;
            size_t gv = ((size_t)bh * DHD + d) * NN + jt * 128 + u * 8;
            CP_ASYNC16(sb + d * VT_B + u * 16, g_vt_h + gv);
        }
        CP_COMMIT();
    };

    issueK(0, stg[0]);
    {   // stage q tile (32 rows x 64 halfs) in ST1
        int r = tid >> 3, u = tid & 7;
        size_t gq = ((size_t)(bh * NN + i0 + r)) * DHD + u * 8;
        *(uint4*)(smc + OFF_ST1 + r * KT_B + u * 16) = *(const uint4*)(g_q_h + gq);
    }
    __syncthreads();
    uint32_t qh[2][4][4];
    #pragma unroll
    for (int m = 0; m < 2; m++)
        #pragma unroll
        for (int ks = 0; ks < 4; ks++) {
            uint32_t a = smb + OFF_ST1 + (m * 16 + (lane & 15)) * KT_B
                       + ks * 32 + (lane >> 4) * 16;
            LDSM4(qh[m][ks][0], qh[m][ks][1], qh[m][ks][2], qh[m][ks][3], a);
        }
    __syncthreads();
    issueK(1, stg[1]);

    float qn10[2][2];
    #pragma unroll
    for (int m = 0; m < 2; m++)
        #pragma unroll
        for (int hf = 0; hf < 2; hf++)
            qn10[m][hf] = g_qni[bh * NN + i0 + m * 16 + g + hf * 8] * 10.0f;

    float rall[2][2] = {}, rpos[2][2] = {}, rsum[2][2] = {};
    int cnt = 0;

    // ---- Phase A: 16 tiles of 64 j, single fp16 MMA term ----
    for (int jt = 0; jt < 16; jt++) {
        if (jt < 15) CP_WAIT1(); else CP_WAIT0();
        __syncthreads();
        const uint32_t sb = stg[jt & 1];

        float acc[2][4] = {};
        #pragma unroll
        for (int kp = 0; kp < 2; kp++) {
            uint32_t kh4[4];
            uint32_t ka = sb + (warp * 8 + lr) * KT_B + kp * 64 + sel * 16;
            LDSM4(kh4[0], kh4[1], kh4[2], kh4[3], ka);
            #pragma unroll
            for (int h2 = 0; h2 < 2; h2++) {
                const int ks = kp * 2 + h2;
                #pragma unroll
                for (int m = 0; m < 2; m++)
                    MMA16816H(acc[m], qh[m][ks], kh4[h2*2], kh4[h2*2+1]);
            }
        }

        const int j0 = jt * 64 + warp * 8 + t * 2;
        float2 kn = *(const float2*)&g_kni[bh * NN + j0];
        #pragma unroll
        for (int m = 0; m < 2; m++)
            #pragma unroll
            for (int hf = 0; hf < 2; hf++) {
                const int il = m * 16 + g + hf * 8;
                int2 mm = *(const int2*)(mask +
                          ((size_t)(b * NN + i0 + il)) * NN + j0);
                float d0 = acc[m][hf * 2 + 0];
                float d1 = acc[m][hf * 2 + 1];
                float qn = qn10[m][hf];
                float ec0 = fexp(d0 * qn * kn.x);
                float ec1 = fexp(d1 * qn * kn.y);
                rall[m][hf] += ec0 + ec1;
                rpos[m][hf] += (mm.x ? ec0 : 0.f) + (mm.y ? ec1 : 0.f);
                cnt += (mm.x != 0) + (mm.y != 0);
                float es0 = mm.x ? fexp(d0 * SCALE) : 0.f;
                float es1 = mm.y ? fexp(d1 * SCALE) : 0.f;
                rsum[m][hf] += es0 + es1;
                *(__half2*)(smc + OFF_ES + il * ES_B + j0 * 2) =
                    __floats2half2_rn(es0, es1);
            }
        __syncthreads();
        if (jt + 2 <= 15) issueK(jt + 2, stg[jt & 1]);
    }

    #pragma unroll
    for (int m = 0; m < 2; m++)
        #pragma unroll
        for (int hf = 0; hf < 2; hf++) {
            #pragma unroll
            for (int o = 1; o <= 2; o <<= 1) {
                rall[m][hf] += __shfl_xor_sync(0xffffffffu, rall[m][hf], o);
                rpos[m][hf] += __shfl_xor_sync(0xffffffffu, rpos[m][hf], o);
                rsum[m][hf] += __shfl_xor_sync(0xffffffffu, rsum[m][hf], o);
            }
        }
    #pragma unroll
    for (int o = 16; o > 0; o >>= 1)
        cnt += __shfl_xor_sync(0xffffffffu, cnt, o);
    if (t == 0) {
        #pragma unroll
        for (int m = 0; m < 2; m++)
            #pragma unroll
            for (int hf = 0; hf < 2; hf++) {
                int il = m * 16 + g + hf * 8;
                red[(warp * 32 + il) * 3 + 0] = rall[m][hf];
                red[(warp * 32 + il) * 3 + 1] = rpos[m][hf];
                red[(warp * 32 + il) * 3 + 2] = rsum[m][hf];
            }
    }
    if (lane == 0) wcnt[warp] = cnt;
    __syncthreads();
    if (tid < 32) {
        float a = 0.f, p = 0.f, s = 0.f;
        #pragma unroll
        for (int w = 0; w < 8; w++) {
            a += red[(w * 32 + tid) * 3 + 0];
            p += red[(w * 32 + tid) * 3 + 1];
            s += red[(w * 32 + tid) * 3 + 2];
        }
        invs[tid] = __frcp_rn(s);
        g_clus[bh * NN + i0 + tid] = -__logf(__fdividef(p, a));
    }
    if (tid == 32) {
        int s = 0;
        #pragma unroll
        for (int w = 0; w < 8; w++) s += wcnt[w];
        atomicAdd(&g_msum, s);
    }
    __syncthreads();

    issueV(0, stg[0]);
    issueV(1, stg[1]);

    #pragma unroll 4
    for (int it = 0; it < 16; it++) {
        int idx = tid + it * 256;
        int row = idx >> 7, u = idx & 127;
        uint4 vh = *(const uint4*)(smc + OFF_ES + row * ES_B + u * 16);
        float s = invs[row];
        const __half2* ph = (const __half2*)&vh;
        float ov[8];
        #pragma unroll
        for (int p2 = 0; p2 < 4; p2++) {
            float2 f = __half22float2(ph[p2]);
            ov[2*p2+0] = f.x * s;
            ov[2*p2+1] = f.y * s;
        }
        float* dst = attn_out + ((size_t)bh * NN + i0 + row) * NN + u * 8;
        *(float4*)dst       = make_float4(ov[0], ov[1], ov[2], ov[3]);
        *(float4*)(dst + 4) = make_float4(ov[4], ov[5], ov[6], ov[7]);
    }

    const int wm = warp >> 2, wd = warp & 3;
    float acc2[2][4] = {};

    for (int jt = 0; jt < 8; jt++) {
        if (jt < 7) CP_WAIT1(); else CP_WAIT0();
        __syncthreads();
        const uint32_t sb = stg[jt & 1];

        #pragma unroll
        for (int ks2 = 0; ks2 < 8; ks2++) {
            uint32_t ah[4], vh4[4];
            uint32_t aa = smb + OFF_ES + (wm * 16 + (lane & 15)) * ES_B
                        + jt * 256 + ks2 * 32 + (lane >> 4) * 16;
            LDSM4(ah[0], ah[1], ah[2], ah[3], aa);
            uint32_t va = sb + (wd * 16 + ((sel >> 1) & 1) * 8 + lr) * VT_B
                        + ks2 * 32 + (sel & 1) * 16;
            LDSM4(vh4[0], vh4[1], vh4[2], vh4[3], va);
            #pragma unroll
            for (int nb = 0; nb < 2; nb++)
                MMA16816H(acc2[nb], ah, vh4[nb*2], vh4[nb*2+1]);
        }
        __syncthreads();
        if (jt + 2 <= 7) issueV(jt + 2, stg[jt & 1]);
    }

    const int h = bh & 7;
    #pragma unroll
    for (int nb = 0; nb < 2; nb++)
        #pragma unroll
        for (int hf = 0; hf < 2; hf++) {
            int i = wm * 16 + g + hf * 8;
            int d = wd * 16 + nb * 8 + t * 2;
            float s = invs[i];
            float v0 = acc2[nb][hf * 2 + 0] * s;
            float v1 = acc2[nb][hf * 2 + 1] * s;
            size_t base = ((size_t)(b * NN + i0 + i)) * INNERD + h * DHD + d;
            *(__half2*)(g_ctx_h + base) = __floats2half2_rn(v0, v1);
        }
}

// ---------------- final dcl scalar ----------------
__global__ void dcl_kernel(float* out_dcl) {
    __shared__ float red[1024];
    const int tid = threadIdx.x;
    float s = 0.f;
    const int base = tid * 32;
    #pragma unroll 8
    for (int i = 0; i < 32; i++) s += g_clus[base + i];
    red[tid] = s;
    __syncthreads();
    for (int o = 512; o > 0; o >>= 1) {
        if (tid < o) red[tid] += red[tid + o];
        __syncthreads();
    }
    if (tid == 0 && out_dcl) {
        float clus_mean = red[0] / (float)NROWS;
        float regular = ((float)(g_msum >> 3) - (float)(BB * NN)) /
                        ((float)BB * (float)NN * (float)(NN - 1));
        out_dcl[0] = clus_mean + 0.3f * regular;
    }
}

// ---------------- launcher ----------------
extern "C" void kernel_launch(void* const* d_in, const int* in_sizes, int n_in,
                              void* d_out, int out_size) {
    const float* x   = (const float*)d_in[0];
    const int*   msk = (const int*)  d_in[1];
    const float* Wq  = (const float*)d_in[2];
    const float* bq  = (const float*)d_in[3];
    const float* Wk  = (const float*)d_in[4];
    const float* bk  = (const float*)d_in[5];
    const float* Wv  = (const float*)d_in[6];
    const float* bv  = (const float*)d_in[7];
    const float* Wo  = (const float*)d_in[8];
    const float* bo  = (const float*)d_in[9];
    float* out = (float*)d_out;

    const size_t OUTE  = (size_t)BB * NN * DIMD;
    const size_t ATTNE = (size_t)BH * NN * NN;

    float* attn_ptr;
    if ((size_t)out_size >= OUTE + ATTNE) {
        attn_ptr = out + OUTE;
    } else {
        void* p = nullptr;
        cudaGetSymbolAddress(&p, g_attn_fb);
        attn_ptr = (float*)p;
    }
    float* dcl_ptr = ((size_t)out_size >= OUTE + ATTNE + 1) ? (out + OUTE + ATTNE)
                                                            : nullptr;

    cudaFuncSetAttribute(attn5_kernel,
                         cudaFuncAttributeMaxDynamicSharedMemorySize, ATTN_SMEM);
    cudaFuncSetAttribute(bmma_kernel,
                         cudaFuncAttributeMaxDynamicSharedMemorySize, BMMA_SMEM);
    cudaFuncSetAttribute(outproj2_kernel,
                         cudaFuncAttributeMaxDynamicSharedMemorySize, OPROJ_SMEM);

    init_kernel<<<1, 32>>>();
    convx_kernel<<<2048, 256>>>(x);
    convw_kernel<<<dim3(16, 16, 4), dim3(32, 8)>>>(Wq, Wk, Wv, Wo);

    dim3 qkvgrid(DIMD / 64, (BB * NN) / 128, 3);   // (8, 32, 3)
    bmma_kernel<<<qkvgrid, 256, BMMA_SMEM>>>(bq, bk, bv);

    attn5_kernel<<<BH * (NN / 32), 256, ATTN_SMEM>>>(msk, attn_ptr);

    dim3 ogrid(DIMD / 64, (BB * NN) / 128);        // (8, 32)
    outproj2_kernel<<<ogrid, 256, OPROJ_SMEM>>>(bo, out);

    dcl_kernel<<<1, 1024>>>(dcl_ptr);
}

// round 16
// speedup vs baseline: 1.3049x; 1.0512x over previous
#include <cuda_runtime.h>
#include <cuda_bf16.h>
#include <cuda_fp16.h>
#include <math.h>
#include <stdint.h>

#define BB 4
#define NN 1024
#define DIMD 512
#define HH 8
#define DHD 64
#define INNERD 512
#define BH (BB*HH)            // 32
#define NROWS (BH*NN)         // 32768
#define SCALE 0.125f

// ---------------- scratch (device globals; no runtime allocation) ----------
__device__ float g_qni[NROWS];              // reciprocal q norms
__device__ float g_kni[NROWS];              // reciprocal k norms
__device__ float g_clus[NROWS];
__device__ int   g_msum;                    // 8 * sum(mask)
__device__ float g_attn_fb[(size_t)BH*NN*NN];
// fp16 operands
__device__ __half g_x_h[(size_t)BB*NN*DIMD];       // fp16 x
__device__ __half g_w_hi[4*512*512];               // W^T fp16 hi, slots q,k,v,o
__device__ __half g_w_lo[4*512*512];               // W^T fp16 lo
__device__ __half g_ctx_h[(size_t)BB*NN*INNERD];   // fp16 ctx
__device__ __half g_q_h[NROWS*DHD];                // fp16 [bh][n][d]
__device__ __half g_k_h[NROWS*DHD];                // fp16 [bh][n][d]
__device__ __half g_vt_h[NROWS*DHD];               // fp16 TRANSPOSED [bh][d][n]

// ---------------- helpers ----------------
__device__ __forceinline__ uint32_t smem_to_u32(const void* p) {
    uint32_t a;
    asm("{ .reg .u64 t; cvta.to.shared.u64 t, %1; cvt.u32.u64 %0, t; }"
        : "=r"(a) : "l"(p));
    return a;
}
#define SMEM_SWZ(off) ((off) ^ (((off) >> 3) & 0x70))

#define LDSM4(R0, R1, R2, R3, ADDR) \
    asm volatile("ldmatrix.sync.aligned.m8n8.x4.shared.b16 {%0,%1,%2,%3}, [%4];" \
        : "=r"(R0), "=r"(R1), "=r"(R2), "=r"(R3) : "r"(ADDR))

#define MMA16816H(C, A, B0, B1) \
    asm volatile("mma.sync.aligned.m16n8k16.row.col.f32.f16.f16.f32 " \
        "{%0,%1,%2,%3}, {%4,%5,%6,%7}, {%8,%9}, {%0,%1,%2,%3};" \
        : "+f"((C)[0]), "+f"((C)[1]), "+f"((C)[2]), "+f"((C)[3]) \
        : "r"((A)[0]), "r"((A)[1]), "r"((A)[2]), "r"((A)[3]), "r"(B0), "r"(B1))

#define CP_ASYNC16(smaddr, gptr) \
    asm volatile("cp.async.cg.shared.global [%0], [%1], 16;" \
        :: "r"(smaddr), "l"(gptr) : "memory")
#define CP_COMMIT() asm volatile("cp.async.commit_group;" ::: "memory")
#define CP_WAIT1() asm volatile("cp.async.wait_group 1;" ::: "memory")
#define CP_WAIT0() asm volatile("cp.async.wait_group 0;" ::: "memory")

// FMA-pipe exp (no MUFU)
__device__ __forceinline__ float fexp(float x) {
    float t = x * 1.4426950408889634f;
    float z = t + 12582912.0f;
    int ni = __float_as_int(z) << 23;
    float f = t - (z - 12582912.0f);
    float p =            1.3333558e-3f;
    p = fmaf(p, f, 9.6181291e-3f);
    p = fmaf(p, f, 5.5504110e-2f);
    p = fmaf(p, f, 2.4022651e-1f);
    p = fmaf(p, f, 6.9314718e-1f);
    p = fmaf(p, f, 1.0f);
    return __int_as_float(__float_as_int(p) + ni);
}

// ---------------- init ----------------
__global__ void init_kernel() {
    if (threadIdx.x == 0 && blockIdx.x == 0) g_msum = 0;
}

// ---------------- convert x -> fp16 ----------------
__global__ void convx_kernel(const float* __restrict__ x) {
    int i = blockIdx.x * blockDim.x + threadIdx.x;
    float4 v = ((const float4*)x)[i];
    __half2* dst = (__half2*)(g_x_h + (size_t)i * 4);
    dst[0] = __floats2half2_rn(v.x, v.y);
    dst[1] = __floats2half2_rn(v.z, v.w);
}

// ---------------- transpose+convert W -> W^T fp16 hi/lo ----------------
__global__ void convw_kernel(const float* __restrict__ Wq,
                             const float* __restrict__ Wk,
                             const float* __restrict__ Wv,
                             const float* __restrict__ Wo)
{
    __shared__ float tile[32][33];
    const int z = blockIdx.z;
    const float* W = (z == 0) ? Wq : (z == 1) ? Wk : (z == 2) ? Wv : Wo;
    const int tx = threadIdx.x, ty = threadIdx.y;
    const int bk = blockIdx.y * 32, bn = blockIdx.x * 32;
    #pragma unroll
    for (int r = 0; r < 4; r++)
        tile[ty + 8*r][tx] = W[(size_t)(bk + ty + 8*r) * 512 + bn + tx];
    __syncthreads();
    #pragma unroll
    for (int r = 0; r < 4; r++) {
        int n = bn + ty + 8*r, k = bk + tx;
        float v = tile[tx][ty + 8*r];
        size_t o = (size_t)z * 262144 + (size_t)n * 512 + k;
        __half h = __float2half_rn(v);
        g_w_hi[o] = h;
        g_w_lo[o] = __float2half_rn(v - __half2float(h));
    }
}

// ================= fp16 2-term HMMA GEMM, 128x64 tile, occ 2 ================
// QKV kernel: z = blockIdx.z (0 q+norms, 1 k+norms, 2 v transposed)
#define OSA    0
#define OSB_HI 16384
#define OSB_LO 24576
#define OSTAGE 32768
#define GEMM_SMEM (2*OSTAGE)

__global__ __launch_bounds__(256, 2)
void qkv_kernel(const float* __restrict__ b0, const float* __restrict__ b1,
                const float* __restrict__ b2)
{
    extern __shared__ char smc[];
    const uint32_t smb = smem_to_u32(smc);
    const int tid = threadIdx.x;
    const int wid = tid >> 5, lane = tid & 31;
    const int z = blockIdx.z;
    const int bm = blockIdx.y * 128, bn = blockIdx.x * 64;

    const __half* Bh = g_w_hi + (size_t)z * 262144;
    const __half* Bl = g_w_lo + (size_t)z * 262144;
    const float* bias = (z == 0) ? b0 : (z == 1) ? b1 : b2;

    float acc[8][4] = {};
    const int ldr = tid >> 3, ldu = tid & 7;

    auto issue = [&](int kc, int st) {
        const uint32_t sb = smb + st * OSTAGE;
        #pragma unroll
        for (int it = 0; it < 4; it++) {
            int r = ldr + it * 32;
            size_t ga = (size_t)(bm + r) * 512 + kc * 64 + ldu * 8;
            uint32_t so = SMEM_SWZ((uint32_t)(r * 128 + ldu * 16));
            CP_ASYNC16(sb + OSA + so, g_x_h + ga);
        }
        #pragma unroll
        for (int it = 0; it < 2; it++) {
            int r = ldr + it * 32;
            size_t gb = (size_t)(bn + r) * 512 + kc * 64 + ldu * 8;
            uint32_t so = SMEM_SWZ((uint32_t)(r * 128 + ldu * 16));
            CP_ASYNC16(sb + OSB_HI + so, Bh + gb);
            CP_ASYNC16(sb + OSB_LO + so, Bl + gb);
        }
        CP_COMMIT();
    };

    issue(0, 0);
    for (int kc = 0; kc < 8; kc++) {
        const int st = kc & 1;
        const uint32_t sb = smb + st * OSTAGE;
        if (kc < 7) { issue(kc + 1, st ^ 1); CP_WAIT1(); }
        else        { CP_WAIT0(); }
        __syncthreads();

        #pragma unroll
        for (int ks = 0; ks < 4; ks++) {
            uint32_t ah[4], bhf[8][2], blf[8][2];
            const int arow = wid * 16 + (lane & 15);
            const int akb  = ks * 32 + (lane >> 4) * 16;
            {
                uint32_t off = SMEM_SWZ((uint32_t)(arow * 128 + akb));
                LDSM4(ah[0], ah[1], ah[2], ah[3], sb + OSA + off);
            }
            const int lr = lane & 7, sel = lane >> 3;
            const int nrow = ((sel >> 1) & 1) * 8 + lr;
            const int bkb  = ks * 32 + (sel & 1) * 16;
            #pragma unroll
            for (int p = 0; p < 4; p++) {
                uint32_t off = SMEM_SWZ((uint32_t)((nrow + p * 16) * 128 + bkb));
                LDSM4(bhf[2*p][0], bhf[2*p][1], bhf[2*p+1][0], bhf[2*p+1][1],
                      sb + OSB_HI + off);
                LDSM4(blf[2*p][0], blf[2*p][1], blf[2*p+1][0], blf[2*p+1][1],
                      sb + OSB_LO + off);
            }
            #pragma unroll
            for (int nb = 0; nb < 8; nb++) {
                MMA16816H(acc[nb], ah, bhf[nb][0], bhf[nb][1]);
                MMA16816H(acc[nb], ah, blf[nb][0], blf[nb][1]);
            }
        }
        __syncthreads();
    }

    // ---------------- epilogue ----------------
    const int g = lane >> 2, t = lane & 3;
    const int h = bn >> 6;
    float2 bv[8];
    #pragma unroll
    for (int nb = 0; nb < 8; nb++)
        bv[nb] = *(const float2*)&bias[bn + nb * 8 + 2 * t];

    #pragma unroll
    for (int half = 0; half < 2; half++) {
        const int rglob = bm + wid * 16 + g + half * 8;
        const int bi = rglob >> 10, n = rglob & 1023;
        float ss = 0.f;
        #pragma unroll
        for (int nb = 0; nb < 8; nb++) {
            float v0 = acc[nb][half * 2 + 0] + bv[nb].x;
            float v1 = acc[nb][half * 2 + 1] + bv[nb].y;
            ss += v0 * v0 + v1 * v1;
            const int d = nb * 8 + 2 * t;
            if (z == 2) {
                size_t vb = ((size_t)(bi*HH + h)*DHD + d)*NN + n;
                g_vt_h[vb]      = __float2half_rn(v0);
                g_vt_h[vb + NN] = __float2half_rn(v1);
            } else {
                __half* dst = (z == 0) ? g_q_h : g_k_h;
                size_t qb = ((size_t)(bi*HH + h)*NN + n)*DHD + d;
                *(__half2*)(dst + qb) = __floats2half2_rn(v0, v1);
            }
        }
        if (z < 2) {
            ss += __shfl_xor_sync(0xffffffffu, ss, 1);
            ss += __shfl_xor_sync(0xffffffffu, ss, 2);
            if (t == 0) {
                float* dst = (z == 0) ? g_qni : g_kni;
                dst[(bi * HH + h) * NN + n] = rsqrtf(ss);
            }
        }
    }
}

// out projection: fp16 ctx @ fp16-split Wo (slot 3)
__global__ __launch_bounds__(256, 2)
void outproj2_kernel(const float* __restrict__ bias, float* __restrict__ out)
{
    extern __shared__ char smc[];
    const uint32_t smb = smem_to_u32(smc);
    const int tid = threadIdx.x;
    const int wid = tid >> 5, lane = tid & 31;
    const int bm = blockIdx.y * 128, bn = blockIdx.x * 64;
    const __half* Bh = g_w_hi + (size_t)3 * 262144;
    const __half* Bl = g_w_lo + (size_t)3 * 262144;

    float acc[8][4] = {};
    const int ldr = tid >> 3, ldu = tid & 7;

    auto issue = [&](int kc, int st) {
        const uint32_t sb = smb + st * OSTAGE;
        #pragma unroll
        for (int it = 0; it < 4; it++) {
            int r = ldr + it * 32;
            size_t ga = (size_t)(bm + r) * 512 + kc * 64 + ldu * 8;
            uint32_t so = SMEM_SWZ((uint32_t)(r * 128 + ldu * 16));
            CP_ASYNC16(sb + OSA + so, g_ctx_h + ga);
        }
        #pragma unroll
        for (int it = 0; it < 2; it++) {
            int r = ldr + it * 32;
            size_t gb = (size_t)(bn + r) * 512 + kc * 64 + ldu * 8;
            uint32_t so = SMEM_SWZ((uint32_t)(r * 128 + ldu * 16));
            CP_ASYNC16(sb + OSB_HI + so, Bh + gb);
            CP_ASYNC16(sb + OSB_LO + so, Bl + gb);
        }
        CP_COMMIT();
    };

    issue(0, 0);
    for (int kc = 0; kc < 8; kc++) {
        const int st = kc & 1;
        const uint32_t sb = smb + st * OSTAGE;
        if (kc < 7) { issue(kc + 1, st ^ 1); CP_WAIT1(); }
        else        { CP_WAIT0(); }
        __syncthreads();

        #pragma unroll
        for (int ks = 0; ks < 4; ks++) {
            uint32_t ah[4], bhf[8][2], blf[8][2];
            const int arow = wid * 16 + (lane & 15);
            const int akb  = ks * 32 + (lane >> 4) * 16;
            {
                uint32_t off = SMEM_SWZ((uint32_t)(arow * 128 + akb));
                LDSM4(ah[0], ah[1], ah[2], ah[3], sb + OSA + off);
            }
            const int lr = lane & 7, sel = lane >> 3;
            const int nrow = ((sel >> 1) & 1) * 8 + lr;
            const int bkb  = ks * 32 + (sel & 1) * 16;
            #pragma unroll
            for (int p = 0; p < 4; p++) {
                uint32_t off = SMEM_SWZ((uint32_t)((nrow + p * 16) * 128 + bkb));
                LDSM4(bhf[2*p][0], bhf[2*p][1], bhf[2*p+1][0], bhf[2*p+1][1],
                      sb + OSB_HI + off);
                LDSM4(blf[2*p][0], blf[2*p][1], blf[2*p+1][0], blf[2*p+1][1],
                      sb + OSB_LO + off);
            }
            #pragma unroll
            for (int nb = 0; nb < 8; nb++) {
                MMA16816H(acc[nb], ah, bhf[nb][0], bhf[nb][1]);
                MMA16816H(acc[nb], ah, blf[nb][0], blf[nb][1]);
            }
        }
        __syncthreads();
    }

    const int g = lane >> 2, t = lane & 3;
    float2 bv[8];
    #pragma unroll
    for (int nb = 0; nb < 8; nb++)
        bv[nb] = *(const float2*)&bias[bn + nb * 8 + 2 * t];

    #pragma unroll
    for (int half = 0; half < 2; half++) {
        const int rglob = bm + wid * 16 + g + half * 8;
        #pragma unroll
        for (int nb = 0; nb < 8; nb++) {
            float v0 = acc[nb][half * 2 + 0] + bv[nb].x;
            float v1 = acc[nb][half * 2 + 1] + bv[nb].y;
            *(float2*)(out + (size_t)rglob * 512 + bn + nb * 8 + 2 * t) =
                make_float2(v0, v1);
        }
    }
}

// ============ fused attention, occ=2: single fp16 q/k/es/v ============
#define ES_B 2064
#define KT_B 144
#define VT_B 272
#define OFF_ES  0
#define OFF_ST0 66048
#define OFF_ST1 84480
#define OFF_RED 102912
#define OFF_INVS 105984
#define OFF_WCNT 106112
#define ATTN_SMEM 106496

__global__ __launch_bounds__(256, 2)
void attn5_kernel(const int* __restrict__ mask, float* __restrict__ attn_out)
{
    extern __shared__ char smc[];
    const uint32_t smb = smem_to_u32(smc);
    float* invs = (float*)(smc + OFF_INVS);
    float* red  = (float*)(smc + OFF_RED);
    int*   wcnt = (int*)(smc + OFF_WCNT);

    const int tid  = threadIdx.x;
    const int warp = tid >> 5, lane = tid & 31;
    const int g = lane >> 2, t = lane & 3;
    const int lr = lane & 7, sel = lane >> 3;
    const int blk = blockIdx.x;             // 1024
    const int bh  = blk >> 5;
    const int i0  = (blk & 31) * 32;
    const int b   = bh >> 3;

    const uint32_t stg[2] = {smb + OFF_ST0, smb + OFF_ST1};

    auto issueK = [&](int jt, uint32_t sb) {
        #pragma unroll
        for (int it = 0; it < 2; it++) {
            int idx = tid + it * 256;
            int r = idx >> 3, u = idx & 7;
            size_t gk = ((size_t)(bh * NN + jt * 64 + r)) * DHD + u * 8;
            CP_ASYNC16(sb + r * KT_B + u * 16, g_k_h + gk);
        }
        CP_COMMIT();
    };
    auto issueV = [&](int jt, uint32_t sb) {
        #pragma unroll
        for (int it = 0; it < 4; it++) {
            int idx = tid + it * 256;
            int d = idx >> 4, u = idx & 15;
            size_t gv = ((size_t)bh * DHD + d) * NN + jt * 128 + u * 8;
            CP_ASYNC16(sb + d * VT_B + u * 16, g_vt_h + gv);
        }
        CP_COMMIT();
    };

    issueK(0, stg[0]);
    {
        int r = tid >> 3, u = tid & 7;
        size_t gq = ((size_t)(bh * NN + i0 + r)) * DHD + u * 8;
        *(uint4*)(smc + OFF_ST1 + r * KT_B + u * 16) = *(const uint4*)(g_q_h + gq);
    }
    __syncthreads();
    uint32_t qh[2][4][4];
    #pragma unroll
    for (int m = 0; m < 2; m++)
        #pragma unroll
        for (int ks = 0; ks < 4; ks++) {
            uint32_t a = smb + OFF_ST1 + (m * 16 + (lane & 15)) * KT_B
                       + ks * 32 + (lane >> 4) * 16;
            LDSM4(qh[m][ks][0], qh[m][ks][1], qh[m][ks][2], qh[m][ks][3], a);
        }
    __syncthreads();
    issueK(1, stg[1]);

    float qn10[2][2];
    #pragma unroll
    for (int m = 0; m < 2; m++)
        #pragma unroll
        for (int hf = 0; hf < 2; hf++)
            qn10[m][hf] = g_qni[bh * NN + i0 + m * 16 + g + hf * 8] * 10.0f;

    float rall[2][2] = {}, rpos[2][2] = {}, rsum[2][2] = {};
    int cnt = 0;

    for (int jt = 0; jt < 16; jt++) {
        if (jt < 15) CP_WAIT1(); else CP_WAIT0();
        __syncthreads();
        const uint32_t sb = stg[jt & 1];

        float acc[2][4] = {};
        #pragma unroll
        for (int kp = 0; kp < 2; kp++) {
            uint32_t kh4[4];
            uint32_t ka = sb + (warp * 8 + lr) * KT_B + kp * 64 + sel * 16;
            LDSM4(kh4[0], kh4[1], kh4[2], kh4[3], ka);
            #pragma unroll
            for (int h2 = 0; h2 < 2; h2++) {
                const int ks = kp * 2 + h2;
                #pragma unroll
                for (int m = 0; m < 2; m++)
                    MMA16816H(acc[m], qh[m][ks], kh4[h2*2], kh4[h2*2+1]);
            }
        }

        const int j0 = jt * 64 + warp * 8 + t * 2;
        float2 kn = *(const float2*)&g_kni[bh * NN + j0];
        #pragma unroll
        for (int m = 0; m < 2; m++)
            #pragma unroll
            for (int hf = 0; hf < 2; hf++) {
                const int il = m * 16 + g + hf * 8;
                int2 mm = *(const int2*)(mask +
                          ((size_t)(b * NN + i0 + il)) * NN + j0);
                float d0 = acc[m][hf * 2 + 0];
                float d1 = acc[m][hf * 2 + 1];
                float qn = qn10[m][hf];
                float ec0 = fexp(d0 * qn * kn.x);
                float ec1 = fexp(d1 * qn * kn.y);
                rall[m][hf] += ec0 + ec1;
                rpos[m][hf] += (mm.x ? ec0 : 0.f) + (mm.y ? ec1 : 0.f);
                cnt += (mm.x != 0) + (mm.y != 0);
                float es0 = mm.x ? fexp(d0 * SCALE) : 0.f;
                float es1 = mm.y ? fexp(d1 * SCALE) : 0.f;
                rsum[m][hf] += es0 + es1;
                *(__half2*)(smc + OFF_ES + il * ES_B + j0 * 2) =
                    __floats2half2_rn(es0, es1);
            }
        __syncthreads();
        if (jt + 2 <= 15) issueK(jt + 2, stg[jt & 1]);
    }

    #pragma unroll
    for (int m = 0; m < 2; m++)
        #pragma unroll
        for (int hf = 0; hf < 2; hf++) {
            #pragma unroll
            for (int o = 1; o <= 2; o <<= 1) {
                rall[m][hf] += __shfl_xor_sync(0xffffffffu, rall[m][hf], o);
                rpos[m][hf] += __shfl_xor_sync(0xffffffffu, rpos[m][hf], o);
                rsum[m][hf] += __shfl_xor_sync(0xffffffffu, rsum[m][hf], o);
            }
        }
    #pragma unroll
    for (int o = 16; o > 0; o >>= 1)
        cnt += __shfl_xor_sync(0xffffffffu, cnt, o);
    if (t == 0) {
        #pragma unroll
        for (int m = 0; m < 2; m++)
            #pragma unroll
            for (int hf = 0; hf < 2; hf++) {
                int il = m * 16 + g + hf * 8;
                red[(warp * 32 + il) * 3 + 0] = rall[m][hf];
                red[(warp * 32 + il) * 3 + 1] = rpos[m][hf];
                red[(warp * 32 + il) * 3 + 2] = rsum[m][hf];
            }
    }
    if (lane == 0) wcnt[warp] = cnt;
    __syncthreads();
    if (tid < 32) {
        float a = 0.f, p = 0.f, s = 0.f;
        #pragma unroll
        for (int w = 0; w < 8; w++) {
            a += red[(w * 32 + tid) * 3 + 0];
            p += red[(w * 32 + tid) * 3 + 1];
            s += red[(w * 32 + tid) * 3 + 2];
        }
        invs[tid] = __frcp_rn(s);
        g_clus[bh * NN + i0 + tid] = -__logf(__fdividef(p, a));
    }
    if (tid == 32) {
        int s = 0;
        #pragma unroll
        for (int w = 0; w < 8; w++) s += wcnt[w];
        atomicAdd(&g_msum, s);
    }
    __syncthreads();

    issueV(0, stg[0]);
    issueV(1, stg[1]);

    #pragma unroll 4
    for (int it = 0; it < 16; it++) {
        int idx = tid + it * 256;
        int row = idx >> 7, u = idx & 127;
        uint4 vh = *(const uint4*)(smc + OFF_ES + row * ES_B + u * 16);
        float s = invs[row];
        const __half2* ph = (const __half2*)&vh;
        float ov[8];
        #pragma unroll
        for (int p2 = 0; p2 < 4; p2++) {
            float2 f = __half22float2(ph[p2]);
            ov[2*p2+0] = f.x * s;
            ov[2*p2+1] = f.y * s;
        }
        float* dst = attn_out + ((size_t)bh * NN + i0 + row) * NN + u * 8;
        *(float4*)dst       = make_float4(ov[0], ov[1], ov[2], ov[3]);
        *(float4*)(dst + 4) = make_float4(ov[4], ov[5], ov[6], ov[7]);
    }

    const int wm = warp >> 2, wd = warp & 3;
    float acc2[2][4] = {};

    for (int jt = 0; jt < 8; jt++) {
        if (jt < 7) CP_WAIT1(); else CP_WAIT0();
        __syncthreads();
        const uint32_t sb = stg[jt & 1];

        #pragma unroll
        for (int ks2 = 0; ks2 < 8; ks2++) {
            uint32_t ah[4], vh4[4];
            uint32_t aa = smb + OFF_ES + (wm * 16 + (lane & 15)) * ES_B
                        + jt * 256 + ks2 * 32 + (lane >> 4) * 16;
            LDSM4(ah[0], ah[1], ah[2], ah[3], aa);
            uint32_t va = sb + (wd * 16 + ((sel >> 1) & 1) * 8 + lr) * VT_B
                        + ks2 * 32 + (sel & 1) * 16;
            LDSM4(vh4[0], vh4[1], vh4[2], vh4[3], va);
            #pragma unroll
            for (int nb = 0; nb < 2; nb++)
                MMA16816H(acc2[nb], ah, vh4[nb*2], vh4[nb*2+1]);
        }
        __syncthreads();
        if (jt + 2 <= 7) issueV(jt + 2, stg[jt & 1]);
    }

    const int h = bh & 7;
    #pragma unroll
    for (int nb = 0; nb < 2; nb++)
        #pragma unroll
        for (int hf = 0; hf < 2; hf++) {
            int i = wm * 16 + g + hf * 8;
            int d = wd * 16 + nb * 8 + t * 2;
            float s = invs[i];
            float v0 = acc2[nb][hf * 2 + 0] * s;
            float v1 = acc2[nb][hf * 2 + 1] * s;
            size_t base = ((size_t)(b * NN + i0 + i)) * INNERD + h * DHD + d;
            *(__half2*)(g_ctx_h + base) = __floats2half2_rn(v0, v1);
        }
}

// ---------------- final dcl scalar ----------------
__global__ void dcl_kernel(float* out_dcl) {
    __shared__ float red[1024];
    const int tid = threadIdx.x;
    float s = 0.f;
    const int base = tid * 32;
    #pragma unroll 8
    for (int i = 0; i < 32; i++) s += g_clus[base + i];
    red[tid] = s;
    __syncthreads();
    for (int o = 512; o > 0; o >>= 1) {
        if (tid < o) red[tid] += red[tid + o];
        __syncthreads();
    }
    if (tid == 0 && out_dcl) {
        float clus_mean = red[0] / (float)NROWS;
        float regular = ((float)(g_msum >> 3) - (float)(BB * NN)) /
                        ((float)BB * (float)NN * (float)(NN - 1));
        out_dcl[0] = clus_mean + 0.3f * regular;
    }
}

// ---------------- launcher ----------------
extern "C" void kernel_launch(void* const* d_in, const int* in_sizes, int n_in,
                              void* d_out, int out_size) {
    const float* x   = (const float*)d_in[0];
    const int*   msk = (const int*)  d_in[1];
    const float* Wq  = (const float*)d_in[2];
    const float* bq  = (const float*)d_in[3];
    const float* Wk  = (const float*)d_in[4];
    const float* bk  = (const float*)d_in[5];
    const float* Wv  = (const float*)d_in[6];
    const float* bv  = (const float*)d_in[7];
    const float* Wo  = (const float*)d_in[8];
    const float* bo  = (const float*)d_in[9];
    float* out = (float*)d_out;

    const size_t OUTE  = (size_t)BB * NN * DIMD;
    const size_t ATTNE = (size_t)BH * NN * NN;

    float* attn_ptr;
    if ((size_t)out_size >= OUTE + ATTNE) {
        attn_ptr = out + OUTE;
    } else {
        void* p = nullptr;
        cudaGetSymbolAddress(&p, g_attn_fb);
        attn_ptr = (float*)p;
    }
    float* dcl_ptr = ((size_t)out_size >= OUTE + ATTNE + 1) ? (out + OUTE + ATTNE)
                                                            : nullptr;

    cudaFuncSetAttribute(attn5_kernel,
                         cudaFuncAttributeMaxDynamicSharedMemorySize, ATTN_SMEM);
    cudaFuncSetAttribute(qkv_kernel,
                         cudaFuncAttributeMaxDynamicSharedMemorySize, GEMM_SMEM);
    cudaFuncSetAttribute(outproj2_kernel,
                         cudaFuncAttributeMaxDynamicSharedMemorySize, GEMM_SMEM);

    init_kernel<<<1, 32>>>();
    convx_kernel<<<2048, 256>>>(x);
    convw_kernel<<<dim3(16, 16, 4), dim3(32, 8)>>>(Wq, Wk, Wv, Wo);

    dim3 qkvgrid(DIMD / 64, (BB * NN) / 128, 3);   // (8, 32, 3)
    qkv_kernel<<<qkvgrid, 256, GEMM_SMEM>>>(bq, bk, bv);

    attn5_kernel<<<BH * (NN / 32), 256, ATTN_SMEM>>>(msk, attn_ptr);

    dim3 ogrid(DIMD / 64, (BB * NN) / 128);        // (8, 32)
    outproj2_kernel<<<ogrid, 256, GEMM_SMEM>>>(bo, out);

    dcl_kernel<<<1, 1024>>>(dcl_ptr);
}

// round 17
// speedup vs baseline: 1.3074x; 1.0019x over previous
#include <cuda_runtime.h>
#include <cuda_bf16.h>
#include <cuda_fp16.h>
#include <math.h>
#include <stdint.h>

#define BB 4
#define NN 1024
#define DIMD 512
#define HH 8
#define DHD 64
#define INNERD 512
#define BH (BB*HH)            // 32
#define NROWS (BH*NN)         // 32768
#define SCALE 0.125f

// ---------------- scratch (device globals; no runtime allocation) ----------
__device__ float g_qni[NROWS];              // reciprocal q norms
__device__ float g_kni[NROWS];              // reciprocal k norms
__device__ float g_clus[NROWS];
__device__ int   g_msum;                    // 8 * sum(mask)
__device__ float g_attn_fb[(size_t)BH*NN*NN];
// fp16 operands
__device__ __half g_x_h[(size_t)BB*NN*DIMD];       // fp16 x
__device__ __half g_w_hi[4*512*512];               // W^T fp16 hi, slots q,k,v,o
__device__ __half g_w_lo[4*512*512];               // W^T fp16 lo
__device__ __half g_ctx_h[(size_t)BB*NN*INNERD];   // fp16 ctx
__device__ __half g_q_h[NROWS*DHD];                // fp16 [bh][n][d]
__device__ __half g_k_h[NROWS*DHD];                // fp16 [bh][n][d]
__device__ __half g_vt_h[NROWS*DHD];               // fp16 TRANSPOSED [bh][d][n]

// ---------------- helpers ----------------
__device__ __forceinline__ uint32_t smem_to_u32(const void* p) {
    uint32_t a;
    asm("{ .reg .u64 t; cvta.to.shared.u64 t, %1; cvt.u32.u64 %0, t; }"
        : "=r"(a) : "l"(p));
    return a;
}
#define SMEM_SWZ(off) ((off) ^ (((off) >> 3) & 0x70))

#define LDSM4(R0, R1, R2, R3, ADDR) \
    asm volatile("ldmatrix.sync.aligned.m8n8.x4.shared.b16 {%0,%1,%2,%3}, [%4];" \
        : "=r"(R0), "=r"(R1), "=r"(R2), "=r"(R3) : "r"(ADDR))

#define MMA16816H(C, A, B0, B1) \
    asm volatile("mma.sync.aligned.m16n8k16.row.col.f32.f16.f16.f32 " \
        "{%0,%1,%2,%3}, {%4,%5,%6,%7}, {%8,%9}, {%0,%1,%2,%3};" \
        : "+f"((C)[0]), "+f"((C)[1]), "+f"((C)[2]), "+f"((C)[3]) \
        : "r"((A)[0]), "r"((A)[1]), "r"((A)[2]), "r"((A)[3]), "r"(B0), "r"(B1))

#define CP_ASYNC16(smaddr, gptr) \
    asm volatile("cp.async.cg.shared.global [%0], [%1], 16;" \
        :: "r"(smaddr), "l"(gptr) : "memory")
#define CP_COMMIT() asm volatile("cp.async.commit_group;" ::: "memory")
#define CP_WAIT2() asm volatile("cp.async.wait_group 2;" ::: "memory")
#define CP_WAIT1() asm volatile("cp.async.wait_group 1;" ::: "memory")
#define CP_WAIT0() asm volatile("cp.async.wait_group 0;" ::: "memory")

// FMA-pipe exp (no MUFU) — used for the softmax path (es)
__device__ __forceinline__ float fexp(float x) {
    float t = x * 1.4426950408889634f;
    float z = t + 12582912.0f;
    int ni = __float_as_int(z) << 23;
    float f = t - (z - 12582912.0f);
    float p =            1.3333558e-3f;
    p = fmaf(p, f, 9.6181291e-3f);
    p = fmaf(p, f, 5.5504110e-2f);
    p = fmaf(p, f, 2.4022651e-1f);
    p = fmaf(p, f, 6.9314718e-1f);
    p = fmaf(p, f, 1.0f);
    return __int_as_float(__float_as_int(p) + ni);
}

// ---------------- init ----------------
__global__ void init_kernel() {
    if (threadIdx.x == 0 && blockIdx.x == 0) g_msum = 0;
}

// ---------------- convert x -> fp16 ----------------
__global__ void convx_kernel(const float* __restrict__ x) {
    int i = blockIdx.x * blockDim.x + threadIdx.x;
    float4 v = ((const float4*)x)[i];
    __half2* dst = (__half2*)(g_x_h + (size_t)i * 4);
    dst[0] = __floats2half2_rn(v.x, v.y);
    dst[1] = __floats2half2_rn(v.z, v.w);
}

// ---------------- transpose+convert W -> W^T fp16 hi/lo ----------------
__global__ void convw_kernel(const float* __restrict__ Wq,
                             const float* __restrict__ Wk,
                             const float* __restrict__ Wv,
                             const float* __restrict__ Wo)
{
    __shared__ float tile[32][33];
    const int z = blockIdx.z;
    const float* W = (z == 0) ? Wq : (z == 1) ? Wk : (z == 2) ? Wv : Wo;
    const int tx = threadIdx.x, ty = threadIdx.y;
    const int bk = blockIdx.y * 32, bn = blockIdx.x * 32;
    #pragma unroll
    for (int r = 0; r < 4; r++)
        tile[ty + 8*r][tx] = W[(size_t)(bk + ty + 8*r) * 512 + bn + tx];
    __syncthreads();
    #pragma unroll
    for (int r = 0; r < 4; r++) {
        int n = bn + ty + 8*r, k = bk + tx;
        float v = tile[tx][ty + 8*r];
        size_t o = (size_t)z * 262144 + (size_t)n * 512 + k;
        __half h = __float2half_rn(v);
        g_w_hi[o] = h;
        g_w_lo[o] = __float2half_rn(v - __half2float(h));
    }
}

// ================= fp16 2-term HMMA GEMM, 128x64 tile, 3 stages, occ 2 ======
#define OSA    0
#define OSB_HI 16384
#define OSB_LO 24576
#define OSTAGE 32768
#define GEMM_SMEM (3*OSTAGE)

__global__ __launch_bounds__(256, 2)
void qkv_kernel(const float* __restrict__ b0, const float* __restrict__ b1,
                const float* __restrict__ b2)
{
    extern __shared__ char smc[];
    const uint32_t smb = smem_to_u32(smc);
    const int tid = threadIdx.x;
    const int wid = tid >> 5, lane = tid & 31;
    const int z = blockIdx.z;
    const int bm = blockIdx.y * 128, bn = blockIdx.x * 64;

    const __half* Bh = g_w_hi + (size_t)z * 262144;
    const __half* Bl = g_w_lo + (size_t)z * 262144;
    const float* bias = (z == 0) ? b0 : (z == 1) ? b1 : b2;

    float acc[8][4] = {};
    const int ldr = tid >> 3, ldu = tid & 7;

    auto issue = [&](int kc, int st) {
        const uint32_t sb = smb + st * OSTAGE;
        #pragma unroll
        for (int it = 0; it < 4; it++) {
            int r = ldr + it * 32;
            size_t ga = (size_t)(bm + r) * 512 + kc * 64 + ldu * 8;
            uint32_t so = SMEM_SWZ((uint32_t)(r * 128 + ldu * 16));
            CP_ASYNC16(sb + OSA + so, g_x_h + ga);
        }
        #pragma unroll
        for (int it = 0; it < 2; it++) {
            int r = ldr + it * 32;
            size_t gb = (size_t)(bn + r) * 512 + kc * 64 + ldu * 8;
            uint32_t so = SMEM_SWZ((uint32_t)(r * 128 + ldu * 16));
            CP_ASYNC16(sb + OSB_HI + so, Bh + gb);
            CP_ASYNC16(sb + OSB_LO + so, Bl + gb);
        }
        CP_COMMIT();
    };

    issue(0, 0);
    issue(1, 1);
    for (int kc = 0; kc < 8; kc++) {
        if (kc + 2 < 8) { issue(kc + 2, (kc + 2) % 3); CP_WAIT2(); }
        else if (kc == 6) CP_WAIT1();
        else              CP_WAIT0();
        __syncthreads();
        const uint32_t sb = smb + (kc % 3) * OSTAGE;

        #pragma unroll
        for (int ks = 0; ks < 4; ks++) {
            uint32_t ah[4], bhf[8][2], blf[8][2];
            const int arow = wid * 16 + (lane & 15);
            const int akb  = ks * 32 + (lane >> 4) * 16;
            {
                uint32_t off = SMEM_SWZ((uint32_t)(arow * 128 + akb));
                LDSM4(ah[0], ah[1], ah[2], ah[3], sb + OSA + off);
            }
            const int lr = lane & 7, sel = lane >> 3;
            const int nrow = ((sel >> 1) & 1) * 8 + lr;
            const int bkb  = ks * 32 + (sel & 1) * 16;
            #pragma unroll
            for (int p = 0; p < 4; p++) {
                uint32_t off = SMEM_SWZ((uint32_t)((nrow + p * 16) * 128 + bkb));
                LDSM4(bhf[2*p][0], bhf[2*p][1], bhf[2*p+1][0], bhf[2*p+1][1],
                      sb + OSB_HI + off);
                LDSM4(blf[2*p][0], blf[2*p][1], blf[2*p+1][0], blf[2*p+1][1],
                      sb + OSB_LO + off);
            }
            #pragma unroll
            for (int nb = 0; nb < 8; nb++) {
                MMA16816H(acc[nb], ah, bhf[nb][0], bhf[nb][1]);
                MMA16816H(acc[nb], ah, blf[nb][0], blf[nb][1]);
            }
        }
        __syncthreads();
    }

    // ---------------- epilogue ----------------
    const int g = lane >> 2, t = lane & 3;
    const int h = bn >> 6;
    float2 bv[8];
    #pragma unroll
    for (int nb = 0; nb < 8; nb++)
        bv[nb] = *(const float2*)&bias[bn + nb * 8 + 2 * t];

    #pragma unroll
    for (int half = 0; half < 2; half++) {
        const int rglob = bm + wid * 16 + g + half * 8;
        const int bi = rglob >> 10, n = rglob & 1023;
        float ss = 0.f;
        #pragma unroll
        for (int nb = 0; nb < 8; nb++) {
            float v0 = acc[nb][half * 2 + 0] + bv[nb].x;
            float v1 = acc[nb][half * 2 + 1] + bv[nb].y;
            ss += v0 * v0 + v1 * v1;
            const int d = nb * 8 + 2 * t;
            if (z == 2) {
                size_t vb = ((size_t)(bi*HH + h)*DHD + d)*NN + n;
                g_vt_h[vb]      = __float2half_rn(v0);
                g_vt_h[vb + NN] = __float2half_rn(v1);
            } else {
                __half* dst = (z == 0) ? g_q_h : g_k_h;
                size_t qb = ((size_t)(bi*HH + h)*NN + n)*DHD + d;
                *(__half2*)(dst + qb) = __floats2half2_rn(v0, v1);
            }
        }
        if (z < 2) {
            ss += __shfl_xor_sync(0xffffffffu, ss, 1);
            ss += __shfl_xor_sync(0xffffffffu, ss, 2);
            if (t == 0) {
                float* dst = (z == 0) ? g_qni : g_kni;
                dst[(bi * HH + h) * NN + n] = rsqrtf(ss);
            }
        }
    }
}

// out projection: fp16 ctx @ fp16-split Wo (slot 3), 3 stages
__global__ __launch_bounds__(256, 2)
void outproj2_kernel(const float* __restrict__ bias, float* __restrict__ out)
{
    extern __shared__ char smc[];
    const uint32_t smb = smem_to_u32(smc);
    const int tid = threadIdx.x;
    const int wid = tid >> 5, lane = tid & 31;
    const int bm = blockIdx.y * 128, bn = blockIdx.x * 64;
    const __half* Bh = g_w_hi + (size_t)3 * 262144;
    const __half* Bl = g_w_lo + (size_t)3 * 262144;

    float acc[8][4] = {};
    const int ldr = tid >> 3, ldu = tid & 7;

    auto issue = [&](int kc, int st) {
        const uint32_t sb = smb + st * OSTAGE;
        #pragma unroll
        for (int it = 0; it < 4; it++) {
            int r = ldr + it * 32;
            size_t ga = (size_t)(bm + r) * 512 + kc * 64 + ldu * 8;
            uint32_t so = SMEM_SWZ((uint32_t)(r * 128 + ldu * 16));
            CP_ASYNC16(sb + OSA + so, g_ctx_h + ga);
        }
        #pragma unroll
        for (int it = 0; it < 2; it++) {
            int r = ldr + it * 32;
            size_t gb = (size_t)(bn + r) * 512 + kc * 64 + ldu * 8;
            uint32_t so = SMEM_SWZ((uint32_t)(r * 128 + ldu * 16));
            CP_ASYNC16(sb + OSB_HI + so, Bh + gb);
            CP_ASYNC16(sb + OSB_LO + so, Bl + gb);
        }
        CP_COMMIT();
    };

    issue(0, 0);
    issue(1, 1);
    for (int kc = 0; kc < 8; kc++) {
        if (kc + 2 < 8) { issue(kc + 2, (kc + 2) % 3); CP_WAIT2(); }
        else if (kc == 6) CP_WAIT1();
        else              CP_WAIT0();
        __syncthreads();
        const uint32_t sb = smb + (kc % 3) * OSTAGE;

        #pragma unroll
        for (int ks = 0; ks < 4; ks++) {
            uint32_t ah[4], bhf[8][2], blf[8][2];
            const int arow = wid * 16 + (lane & 15);
            const int akb  = ks * 32 + (lane >> 4) * 16;
            {
                uint32_t off = SMEM_SWZ((uint32_t)(arow * 128 + akb));
                LDSM4(ah[0], ah[1], ah[2], ah[3], sb + OSA + off);
            }
            const int lr = lane & 7, sel = lane >> 3;
            const int nrow = ((sel >> 1) & 1) * 8 + lr;
            const int bkb  = ks * 32 + (sel & 1) * 16;
            #pragma unroll
            for (int p = 0; p < 4; p++) {
                uint32_t off = SMEM_SWZ((uint32_t)((nrow + p * 16) * 128 + bkb));
                LDSM4(bhf[2*p][0], bhf[2*p][1], bhf[2*p+1][0], bhf[2*p+1][1],
                      sb + OSB_HI + off);
                LDSM4(blf[2*p][0], blf[2*p][1], blf[2*p+1][0], blf[2*p+1][1],
                      sb + OSB_LO + off);
            }
            #pragma unroll
            for (int nb = 0; nb < 8; nb++) {
                MMA16816H(acc[nb], ah, bhf[nb][0], bhf[nb][1]);
                MMA16816H(acc[nb], ah, blf[nb][0], blf[nb][1]);
            }
        }
        __syncthreads();
    }

    const int g = lane >> 2, t = lane & 3;
    float2 bv[8];
    #pragma unroll
    for (int nb = 0; nb < 8; nb++)
        bv[nb] = *(const float2*)&bias[bn + nb * 8 + 2 * t];

    #pragma unroll
    for (int half = 0; half < 2; half++) {
        const int rglob = bm + wid * 16 + g + half * 8;
        #pragma unroll
        for (int nb = 0; nb < 8; nb++) {
            float v0 = acc[nb][half * 2 + 0] + bv[nb].x;
            float v1 = acc[nb][half * 2 + 1] + bv[nb].y;
            *(float2*)(out + (size_t)rglob * 512 + bn + nb * 8 + 2 * t) =
                make_float2(v0, v1);
        }
    }
}

// ============ fused attention, occ=2: fp16 MMAs, split-pipe exp ============
#define ES_B 2064
#define KT_B 144
#define VT_B 272
#define OFF_ES  0
#define OFF_ST0 66048
#define OFF_ST1 84480
#define OFF_RED 102912
#define OFF_INVS 105984
#define OFF_WCNT 106112
#define ATTN_SMEM 106496

__global__ __launch_bounds__(256, 2)
void attn5_kernel(const int* __restrict__ mask, float* __restrict__ attn_out)
{
    extern __shared__ char smc[];
    const uint32_t smb = smem_to_u32(smc);
    float* invs = (float*)(smc + OFF_INVS);
    float* red  = (float*)(smc + OFF_RED);
    int*   wcnt = (int*)(smc + OFF_WCNT);

    const int tid  = threadIdx.x;
    const int warp = tid >> 5, lane = tid & 31;
    const int g = lane >> 2, t = lane & 3;
    const int lr = lane & 7, sel = lane >> 3;
    const int blk = blockIdx.x;             // 1024
    const int bh  = blk >> 5;
    const int i0  = (blk & 31) * 32;
    const int b   = bh >> 3;

    const uint32_t stg[2] = {smb + OFF_ST0, smb + OFF_ST1};

    auto issueK = [&](int jt, uint32_t sb) {
        #pragma unroll
        for (int it = 0; it < 2; it++) {
            int idx = tid + it * 256;
            int r = idx >> 3, u = idx & 7;
            size_t gk = ((size_t)(bh * NN + jt * 64 + r)) * DHD + u * 8;
            CP_ASYNC16(sb + r * KT_B + u * 16, g_k_h + gk);
        }
        CP_COMMIT();
    };
    auto issueV = [&](int jt, uint32_t sb) {
        #pragma unroll
        for (int it = 0; it < 4; it++) {
            int idx = tid + it * 256;
            int d = idx >> 4, u = idx & 15;
            size_t gv = ((size_t)bh * DHD + d) * NN + jt * 128 + u * 8;
            CP_ASYNC16(sb + d * VT_B + u * 16, g_vt_h + gv);
        }
        CP_COMMIT();
    };

    issueK(0, stg[0]);
    {
        int r = tid >> 3, u = tid & 7;
        size_t gq = ((size_t)(bh * NN + i0 + r)) * DHD + u * 8;
        *(uint4*)(smc + OFF_ST1 + r * KT_B + u * 16) = *(const uint4*)(g_q_h + gq);
    }
    __syncthreads();
    uint32_t qh[2][4][4];
    #pragma unroll
    for (int m = 0; m < 2; m++)
        #pragma unroll
        for (int ks = 0; ks < 4; ks++) {
            uint32_t a = smb + OFF_ST1 + (m * 16 + (lane & 15)) * KT_B
                       + ks * 32 + (lane >> 4) * 16;
            LDSM4(qh[m][ks][0], qh[m][ks][1], qh[m][ks][2], qh[m][ks][3], a);
        }
    __syncthreads();
    issueK(1, stg[1]);

    float qn10[2][2];
    #pragma unroll
    for (int m = 0; m < 2; m++)
        #pragma unroll
        for (int hf = 0; hf < 2; hf++)
            qn10[m][hf] = g_qni[bh * NN + i0 + m * 16 + g + hf * 8] * 10.0f;

    float rall[2][2] = {}, rpos[2][2] = {}, rsum[2][2] = {};
    int cnt = 0;

    for (int jt = 0; jt < 16; jt++) {
        if (jt < 15) CP_WAIT1(); else CP_WAIT0();
        __syncthreads();
        const uint32_t sb = stg[jt & 1];

        float acc[2][4] = {};
        #pragma unroll
        for (int kp = 0; kp < 2; kp++) {
            uint32_t kh4[4];
            uint32_t ka = sb + (warp * 8 + lr) * KT_B + kp * 64 + sel * 16;
            LDSM4(kh4[0], kh4[1], kh4[2], kh4[3], ka);
            #pragma unroll
            for (int h2 = 0; h2 < 2; h2++) {
                const int ks = kp * 2 + h2;
                #pragma unroll
                for (int m = 0; m < 2; m++)
                    MMA16816H(acc[m], qh[m][ks], kh4[h2*2], kh4[h2*2+1]);
            }
        }

        const int j0 = jt * 64 + warp * 8 + t * 2;
        float2 kn = *(const float2*)&g_kni[bh * NN + j0];
        #pragma unroll
        for (int m = 0; m < 2; m++)
            #pragma unroll
            for (int hf = 0; hf < 2; hf++) {
                const int il = m * 16 + g + hf * 8;
                int2 mm = *(const int2*)(mask +
                          ((size_t)(b * NN + i0 + il)) * NN + j0);
                float d0 = acc[m][hf * 2 + 0];
                float d1 = acc[m][hf * 2 + 1];
                float qn = qn10[m][hf];
                // contrastive exp on MUFU pipe (concurrent with FMA below)
                float ec0 = __expf(d0 * qn * kn.x);
                float ec1 = __expf(d1 * qn * kn.y);
                rall[m][hf] += ec0 + ec1;
                rpos[m][hf] += (mm.x ? ec0 : 0.f) + (mm.y ? ec1 : 0.f);
                cnt += (mm.x != 0) + (mm.y != 0);
                // softmax exp on FMA pipe
                float es0 = mm.x ? fexp(d0 * SCALE) : 0.f;
                float es1 = mm.y ? fexp(d1 * SCALE) : 0.f;
                rsum[m][hf] += es0 + es1;
                *(__half2*)(smc + OFF_ES + il * ES_B + j0 * 2) =
                    __floats2half2_rn(es0, es1);
            }
        __syncthreads();
        if (jt + 2 <= 15) issueK(jt + 2, stg[jt & 1]);
    }

    #pragma unroll
    for (int m = 0; m < 2; m++)
        #pragma unroll
        for (int hf = 0; hf < 2; hf++) {
            #pragma unroll
            for (int o = 1; o <= 2; o <<= 1) {
                rall[m][hf] += __shfl_xor_sync(0xffffffffu, rall[m][hf], o);
                rpos[m][hf] += __shfl_xor_sync(0xffffffffu, rpos[m][hf], o);
                rsum[m][hf] += __shfl_xor_sync(0xffffffffu, rsum[m][hf], o);
            }
        }
    #pragma unroll
    for (int o = 16; o > 0; o >>= 1)
        cnt += __shfl_xor_sync(0xffffffffu, cnt, o);
    if (t == 0) {
        #pragma unroll
        for (int m = 0; m < 2; m++)
            #pragma unroll
            for (int hf = 0; hf < 2; hf++) {
                int il = m * 16 + g + hf * 8;
                red[(warp * 32 + il) * 3 + 0] = rall[m][hf];
                red[(warp * 32 + il) * 3 + 1] = rpos[m][hf];
                red[(warp * 32 + il) * 3 + 2] = rsum[m][hf];
            }
    }
    if (lane == 0) wcnt[warp] = cnt;
    __syncthreads();
    if (tid < 32) {
        float a = 0.f, p = 0.f, s = 0.f;
        #pragma unroll
        for (int w = 0; w < 8; w++) {
            a += red[(w * 32 + tid) * 3 + 0];
            p += red[(w * 32 + tid) * 3 + 1];
            s += red[(w * 32 + tid) * 3 + 2];
        }
        invs[tid] = __frcp_rn(s);
        g_clus[bh * NN + i0 + tid] = -__logf(__fdividef(p, a));
    }
    if (tid == 32) {
        int s = 0;
        #pragma unroll
        for (int w = 0; w < 8; w++) s += wcnt[w];
        atomicAdd(&g_msum, s);
    }
    __syncthreads();

    issueV(0, stg[0]);
    issueV(1, stg[1]);

    #pragma unroll 4
    for (int it = 0; it < 16; it++) {
        int idx = tid + it * 256;
        int row = idx >> 7, u = idx & 127;
        uint4 vh = *(const uint4*)(smc + OFF_ES + row * ES_B + u * 16);
        float s = invs[row];
        const __half2* ph = (const __half2*)&vh;
        float ov[8];
        #pragma unroll
        for (int p2 = 0; p2 < 4; p2++) {
            float2 f = __half22float2(ph[p2]);
            ov[2*p2+0] = f.x * s;
            ov[2*p2+1] = f.y * s;
        }
        float* dst = attn_out + ((size_t)bh * NN + i0 + row) * NN + u * 8;
        *(float4*)dst       = make_float4(ov[0], ov[1], ov[2], ov[3]);
        *(float4*)(dst + 4) = make_float4(ov[4], ov[5], ov[6], ov[7]);
    }

    const int wm = warp >> 2, wd = warp & 3;
    float acc2[2][4] = {};

    for (int jt = 0; jt < 8; jt++) {
        if (jt < 7) CP_WAIT1(); else CP_WAIT0();
        __syncthreads();
        const uint32_t sb = stg[jt & 1];

        #pragma unroll
        for (int ks2 = 0; ks2 < 8; ks2++) {
            uint32_t ah[4], vh4[4];
            uint32_t aa = smb + OFF_ES + (wm * 16 + (lane & 15)) * ES_B
                        + jt * 256 + ks2 * 32 + (lane >> 4) * 16;
            LDSM4(ah[0], ah[1], ah[2], ah[3], aa);
            uint32_t va = sb + (wd * 16 + ((sel >> 1) & 1) * 8 + lr) * VT_B
                        + ks2 * 32 + (sel & 1) * 16;
            LDSM4(vh4[0], vh4[1], vh4[2], vh4[3], va);
            #pragma unroll
            for (int nb = 0; nb < 2; nb++)
                MMA16816H(acc2[nb], ah, vh4[nb*2], vh4[nb*2+1]);
        }
        __syncthreads();
        if (jt + 2 <= 7) issueV(jt + 2, stg[jt & 1]);
    }

    const int h = bh & 7;
    #pragma unroll
    for (int nb = 0; nb < 2; nb++)
        #pragma unroll
        for (int hf = 0; hf < 2; hf++) {
            int i = wm * 16 + g + hf * 8;
            int d = wd * 16 + nb * 8 + t * 2;
            float s = invs[i];
            float v0 = acc2[nb][hf * 2 + 0] * s;
            float v1 = acc2[nb][hf * 2 + 1] * s;
            size_t base = ((size_t)(b * NN + i0 + i)) * INNERD + h * DHD + d;
            *(__half2*)(g_ctx_h + base) = __floats2half2_rn(v0, v1);
        }
}

// ---------------- final dcl scalar ----------------
__global__ void dcl_kernel(float* out_dcl) {
    __shared__ float red[1024];
    const int tid = threadIdx.x;
    float s = 0.f;
    const int base = tid * 32;
    #pragma unroll 8
    for (int i = 0; i < 32; i++) s += g_clus[base + i];
    red[tid] = s;
    __syncthreads();
    for (int o = 512; o > 0; o >>= 1) {
        if (tid < o) red[tid] += red[tid + o];
        __syncthreads();
    }
    if (tid == 0 && out_dcl) {
        float clus_mean = red[0] / (float)NROWS;
        float regular = ((float)(g_msum >> 3) - (float)(BB * NN)) /
                        ((float)BB * (float)NN * (float)(NN - 1));
        out_dcl[0] = clus_mean + 0.3f * regular;
    }
}

// ---------------- launcher ----------------
extern "C" void kernel_launch(void* const* d_in, const int* in_sizes, int n_in,
                              void* d_out, int out_size) {
    const float* x   = (const float*)d_in[0];
    const int*   msk = (const int*)  d_in[1];
    const float* Wq  = (const float*)d_in[2];
    const float* bq  = (const float*)d_in[3];
    const float* Wk  = (const float*)d_in[4];
    const float* bk  = (const float*)d_in[5];
    const float* Wv  = (const float*)d_in[6];
    const float* bv  = (const float*)d_in[7];
    const float* Wo  = (const float*)d_in[8];
    const float* bo  = (const float*)d_in[9];
    float* out = (float*)d_out;

    const size_t OUTE  = (size_t)BB * NN * DIMD;
    const size_t ATTNE = (size_t)BH * NN * NN;

    float* attn_ptr;
    if ((size_t)out_size >= OUTE + ATTNE) {
        attn_ptr = out + OUTE;
    } else {
        void* p = nullptr;
        cudaGetSymbolAddress(&p, g_attn_fb);
        attn_ptr = (float*)p;
    }
    float* dcl_ptr = ((size_t)out_size >= OUTE + ATTNE + 1) ? (out + OUTE + ATTNE)
                                                            : nullptr;

    cudaFuncSetAttribute(attn5_kernel,
                         cudaFuncAttributeMaxDynamicSharedMemorySize, ATTN_SMEM);
    cudaFuncSetAttribute(qkv_kernel,
                         cudaFuncAttributeMaxDynamicSharedMemorySize, GEMM_SMEM);
    cudaFuncSetAttribute(outproj2_kernel,
                         cudaFuncAttributeMaxDynamicSharedMemorySize, GEMM_SMEM);

    init_kernel<<<1, 32>>>();
    convx_kernel<<<2048, 256>>>(x);
    convw_kernel<<<dim3(16, 16, 4), dim3(32, 8)>>>(Wq, Wk, Wv, Wo);

    dim3 qkvgrid(DIMD / 64, (BB * NN) / 128, 3);   // (8, 32, 3)
    qkv_kernel<<<qkvgrid, 256, GEMM_SMEM>>>(bq, bk, bv);

    attn5_kernel<<<BH * (NN / 32), 256, ATTN_SMEM>>>(msk, attn_ptr);

    dim3 ogrid(DIMD / 64, (BB * NN) / 128);        // (8, 32)
    outproj2_kernel<<<ogrid, 256, GEMM_SMEM>>>(bo, out);

    dcl_kernel<<<1, 1024>>>(dcl_ptr);
}